// round 8
// baseline (speedup 1.0000x reference)
#include <cuda_runtime.h>
#include <cstdint>
#include <math.h>

// ============================================================================
// AttentionModel: QKV projection + MHA + jax-threefry dropout.
//   B=2, S=2048, D=1024, H=16, HD=64
// Round 8: warp-specialized attention — 8 consumer warps (tf32 mma flash
// attention) + 4 producer warps generating threefry dropout-mask words for
// tile kt+1 into a double-buffered smem ring while consumers compute tile kt.
// Projections: 3x tf32-mma GEMM launches (measured 215us in R5).
// ============================================================================

static constexpr int B_ = 2, H_ = 16, S_ = 2048, D_ = 1024, HD_ = 64;

__device__ float g_q[B_ * S_ * D_];
__device__ float g_k[B_ * S_ * D_];
__device__ float g_v[B_ * S_ * D_];

// ---------------------------------------------------------------------------
// tf32 helpers
// ---------------------------------------------------------------------------
__device__ __forceinline__ float f2tf32f(float x) {
    uint32_t r;
    asm("cvt.rna.tf32.f32 %0, %1;" : "=r"(r) : "f"(x));
    return __uint_as_float(r);
}

__device__ __forceinline__ void mma_tf32(float c[4],
                                         uint32_t a0, uint32_t a1, uint32_t a2, uint32_t a3,
                                         uint32_t b0, uint32_t b1) {
    asm volatile(
        "mma.sync.aligned.m16n8k8.row.col.f32.tf32.tf32.f32 "
        "{%0,%1,%2,%3}, {%4,%5,%6,%7}, {%8,%9}, {%0,%1,%2,%3};"
        : "+f"(c[0]), "+f"(c[1]), "+f"(c[2]), "+f"(c[3])
        : "r"(a0), "r"(a1), "r"(a2), "r"(a3), "r"(b0), "r"(b1));
}

// ---------------------------------------------------------------------------
// Threefry-2x32 (JAX partitionable) — verified exact in Round 2.
// keep(idx) <=> bits < 3865470464u (exact integer form of u < 0.9f).
// ---------------------------------------------------------------------------
struct KeyPair { unsigned a, b; };

__host__ __device__ constexpr unsigned rotlc(unsigned x, int r) {
    return (x << r) | (x >> (32 - r));
}

__host__ __device__ constexpr KeyPair threefry_block(unsigned k0, unsigned k1,
                                                     unsigned x0, unsigned x1) {
    unsigned k2 = k0 ^ k1 ^ 0x1BD11BDAu;
    x0 += k0; x1 += k1;
    const int RA[4] = {13, 15, 26, 6};
    const int RB[4] = {17, 29, 16, 24};
    for (int i = 0; i < 4; i++) { x0 += x1; x1 = rotlc(x1, RA[i]); x1 ^= x0; }
    x0 += k1; x1 += k2 + 1u;
    for (int i = 0; i < 4; i++) { x0 += x1; x1 = rotlc(x1, RB[i]); x1 ^= x0; }
    x0 += k2; x1 += k0 + 2u;
    for (int i = 0; i < 4; i++) { x0 += x1; x1 = rotlc(x1, RA[i]); x1 ^= x0; }
    x0 += k0; x1 += k1 + 3u;
    for (int i = 0; i < 4; i++) { x0 += x1; x1 = rotlc(x1, RB[i]); x1 ^= x0; }
    x0 += k1; x1 += k2 + 4u;
    for (int i = 0; i < 4; i++) { x0 += x1; x1 = rotlc(x1, RA[i]); x1 ^= x0; }
    x0 += k2; x1 += k0 + 5u;
    return {x0, x1};
}

__device__ __forceinline__ bool keep_bit(unsigned idx) {
    constexpr KeyPair FK = threefry_block(0u, 0u, 0u, 12345u);
    KeyPair r = threefry_block(FK.a, FK.b, 0u, idx);
    return (r.a ^ r.b) < 3865470464u;
}

// ---------------------------------------------------------------------------
// Projection GEMM (tf32 mma): Y[4096,1024] = X @ W^T + bias (R5 version)
// ---------------------------------------------------------------------------
__global__ void __launch_bounds__(256) proj_mma_kernel(const float* __restrict__ X,
                                                       const float* __restrict__ W,
                                                       const float* __restrict__ bias,
                                                       float* __restrict__ Y) {
    __shared__ float Xs[128 * 36];
    __shared__ float Ws[64 * 36];

    const int m0 = blockIdx.x << 7;
    const int n0 = blockIdx.y << 6;
    const int t  = threadIdx.x;
    const int lane = t & 31, w = t >> 5;
    const int grp = lane >> 2, qd = lane & 3;
    const int wm = w >> 1, wn = w & 1;
    const int frow = t >> 3;
    const int fc4  = (t & 7) << 2;

    float acc[2][4][4];
    #pragma unroll
    for (int mt = 0; mt < 2; mt++)
        #pragma unroll
        for (int nt = 0; nt < 4; nt++)
            #pragma unroll
            for (int r = 0; r < 4; r++) acc[mt][nt][r] = 0.0f;

    const float* xa0 = &Xs[(wm * 32 + grp) * 36 + qd];
    const float* xa1 = &Xs[(wm * 32 + 16 + grp) * 36 + qd];
    const float* wb  = &Ws[(wn * 32 + grp) * 36 + qd];

    for (int k0 = 0; k0 < D_; k0 += 32) {
        __syncthreads();
        #pragma unroll
        for (int l = 0; l < 4; l++) {
            const int row = frow + (l << 5);
            float4 v = *reinterpret_cast<const float4*>(&X[(size_t)(m0 + row) * D_ + k0 + fc4]);
            float* d = &Xs[row * 36 + fc4];
            d[0] = f2tf32f(v.x); d[1] = f2tf32f(v.y); d[2] = f2tf32f(v.z); d[3] = f2tf32f(v.w);
        }
        #pragma unroll
        for (int l = 0; l < 2; l++) {
            const int row = frow + (l << 5);
            float4 v = *reinterpret_cast<const float4*>(&W[(size_t)(n0 + row) * D_ + k0 + fc4]);
            float* d = &Ws[row * 36 + fc4];
            d[0] = f2tf32f(v.x); d[1] = f2tf32f(v.y); d[2] = f2tf32f(v.z); d[3] = f2tf32f(v.w);
        }
        __syncthreads();

        #pragma unroll
        for (int k8 = 0; k8 < 4; k8++) {
            const int kk = k8 << 3;
            uint32_t a[2][4];
            #pragma unroll
            for (int mt = 0; mt < 2; mt++) {
                const float* base = mt ? xa1 : xa0;
                a[mt][0] = __float_as_uint(base[kk]);
                a[mt][1] = __float_as_uint(base[8 * 36 + kk]);
                a[mt][2] = __float_as_uint(base[kk + 4]);
                a[mt][3] = __float_as_uint(base[8 * 36 + kk + 4]);
            }
            #pragma unroll
            for (int nt = 0; nt < 4; nt++) {
                uint32_t b0 = __float_as_uint(wb[nt * 8 * 36 + kk]);
                uint32_t b1 = __float_as_uint(wb[nt * 8 * 36 + kk + 4]);
                mma_tf32(acc[0][nt], a[0][0], a[0][1], a[0][2], a[0][3], b0, b1);
                mma_tf32(acc[1][nt], a[1][0], a[1][1], a[1][2], a[1][3], b0, b1);
            }
        }
    }

    #pragma unroll
    for (int mt = 0; mt < 2; mt++) {
        const int r0 = m0 + wm * 32 + mt * 16 + grp;
        #pragma unroll
        for (int nt = 0; nt < 4; nt++) {
            const int c = n0 + wn * 32 + nt * 8 + (qd << 1);
            const float b0 = bias[c], b1 = bias[c + 1];
            float2 v0 = make_float2(acc[mt][nt][0] + b0, acc[mt][nt][1] + b1);
            float2 v1 = make_float2(acc[mt][nt][2] + b0, acc[mt][nt][3] + b1);
            *reinterpret_cast<float2*>(&Y[(size_t)r0 * D_ + c]) = v0;
            *reinterpret_cast<float2*>(&Y[(size_t)(r0 + 8) * D_ + c]) = v1;
        }
    }
}

// ---------------------------------------------------------------------------
// Warp-specialized flash attention: grid (S/128, B*H), 384 thr.
//   warps 0-7  : consumers (tf32 mma, online softmax, dropout from smem bits)
//   warps 8-11 : producers (threefry mask words for tile kt+1, double buffer)
// smem: Qs[128][72] | Ks[64][72] | Vs[64][72] | Ps[128][72] | Ms[64] | Mb[2][256]
// ---------------------------------------------------------------------------
static constexpr int ATTN_SMEM_FLOATS = 128 * 72 + 64 * 72 + 64 * 72 + 128 * 72 + 64 + 512;
static constexpr int ATTN_SMEM_BYTES  = ATTN_SMEM_FLOATS * 4;

__global__ void __launch_bounds__(384, 1) attn_mma_kernel(const int* __restrict__ mask,
                                                          const float* __restrict__ inv_scale_p,
                                                          float* __restrict__ out) {
    extern __shared__ float sm[];
    float*    Qs = sm;                        // 128 x 72, xor-swizzled quads
    float*    Ks = Qs + 128 * 72;             // 64 x 72, xor-swizzled
    float*    Vs = Ks + 64 * 72;              // 64 x 72, plain
    float*    Ps = Vs + 64 * 72;              // 128 x 72, xor-swizzled
    int*      Ms = (int*)(Ps + 128 * 72);     // 64 key-mask ints
    unsigned* Mb = (unsigned*)(Ms + 64);      // [2][256] dropout words (row*2+h)

    const int q0 = blockIdx.x << 7;
    const int bh = blockIdx.y;
    const int b  = bh >> 4;
    const int hcol = (bh & 15) << 6;
    const int t = threadIdx.x;
    const int lane = t & 31, w = t >> 5;
    const unsigned rowg0 = (unsigned)bh * (unsigned)S_ + (unsigned)q0;  // global q-row base

    // ======================= PRODUCER WARPS (8..11) =======================
    if (w >= 8) {
        const int pw = w - 8;  // 0..3, rows [pw*32, pw*32+32)
        // prologue: tile 0 into buffer 0
        {
            #pragma unroll 4
            for (int i = 0; i < 16; i++) {
                const int row = pw * 32 + 2 * i;
                const unsigned rba = (rowg0 + (unsigned)row) * (unsigned)S_;
                const unsigned rbb = rba + (unsigned)S_;
                const bool a0 = keep_bit(rba + lane);
                const bool a1 = keep_bit(rba + 32u + lane);
                const bool b0 = keep_bit(rbb + lane);
                const bool b1 = keep_bit(rbb + 32u + lane);
                const unsigned wa0 = __ballot_sync(0xffffffffu, a0);
                const unsigned wa1 = __ballot_sync(0xffffffffu, a1);
                const unsigned wb0 = __ballot_sync(0xffffffffu, b0);
                const unsigned wb1 = __ballot_sync(0xffffffffu, b1);
                if (lane == 0) Mb[row * 2 + 0] = wa0;
                if (lane == 1) Mb[row * 2 + 1] = wa1;
                if (lane == 2) Mb[row * 2 + 2] = wb0;
                if (lane == 3) Mb[row * 2 + 3] = wb1;
            }
        }
        for (int kt = 0; kt < S_ / 64; kt++) {
            __syncthreads();  // (A): consumers done reading buf[(kt+1)&1] (last read at kt-1)
            const int nt2 = kt + 1;
            if (nt2 < S_ / 64) {
                unsigned* dst = Mb + ((nt2 & 1) << 8);
                const unsigned cbase = (unsigned)(nt2 << 6);
                #pragma unroll 4
                for (int i = 0; i < 16; i++) {
                    const int row = pw * 32 + 2 * i;
                    const unsigned rba = (rowg0 + (unsigned)row) * (unsigned)S_ + cbase;
                    const unsigned rbb = rba + (unsigned)S_;
                    const bool a0 = keep_bit(rba + lane);
                    const bool a1 = keep_bit(rba + 32u + lane);
                    const bool b0 = keep_bit(rbb + lane);
                    const bool b1 = keep_bit(rbb + 32u + lane);
                    const unsigned wa0 = __ballot_sync(0xffffffffu, a0);
                    const unsigned wa1 = __ballot_sync(0xffffffffu, a1);
                    const unsigned wb0 = __ballot_sync(0xffffffffu, b0);
                    const unsigned wb1 = __ballot_sync(0xffffffffu, b1);
                    if (lane == 0) dst[row * 2 + 0] = wa0;
                    if (lane == 1) dst[row * 2 + 1] = wa1;
                    if (lane == 2) dst[row * 2 + 2] = wb0;
                    if (lane == 3) dst[row * 2 + 3] = wb1;
                }
            }
        }
        return;
    }

    // ======================= CONSUMER WARPS (0..7) ========================
    const int grp = lane >> 2, qd = lane & 3;
    const int R0 = (w << 4) + grp;
    const int sw0 = R0 & 15, sw1 = (R0 + 8) & 15;
    const float scale = 1.0f / inv_scale_p[0];

    float* Q0 = &Qs[R0 * 72];
    float* Q1 = &Qs[(R0 + 8) * 72];
    float* P0 = &Ps[R0 * 72];
    float* P1 = &Ps[(R0 + 8) * 72];

    // ---- load Q tile (swizzled, tf32); t in [0,256) here ----
    {
        const int cq = t & 15;
        #pragma unroll
        for (int l = 0; l < 8; l++) {
            const int row = (t >> 4) + (l << 4);
            float4 v = *reinterpret_cast<const float4*>(
                &g_q[(size_t)(b * S_ + q0 + row) * D_ + hcol + (cq << 2)]);
            float* d = &Qs[row * 72 + ((cq ^ (row & 15)) << 2)];
            d[0] = f2tf32f(v.x); d[1] = f2tf32f(v.y); d[2] = f2tf32f(v.z); d[3] = f2tf32f(v.w);
        }
    }

    float oacc[8][4];
    #pragma unroll
    for (int nt = 0; nt < 8; nt++)
        #pragma unroll
        for (int r = 0; r < 4; r++) oacc[nt][r] = 0.0f;
    float mrow0 = -INFINITY, mrow1 = -INFINITY;
    float lrow0 = 0.0f, lrow1 = 0.0f;

    for (int kt = 0; kt < S_ / 64; kt++) {
        const int kbase = kt << 6;
        __syncthreads();  // (A): joint with producers
        // ---- K/V tile fill (consumers only) ----
        {
            const int cq = t & 15;
            #pragma unroll
            for (int l = 0; l < 4; l++) {
                const int row = (t >> 4) + (l << 4);
                const size_t gof = (size_t)(b * S_ + kbase + row) * D_ + hcol + (cq << 2);
                float4 kv = *reinterpret_cast<const float4*>(&g_k[gof]);
                float* dk = &Ks[row * 72 + ((cq ^ (row & 15)) << 2)];
                dk[0] = f2tf32f(kv.x); dk[1] = f2tf32f(kv.y);
                dk[2] = f2tf32f(kv.z); dk[3] = f2tf32f(kv.w);
                float4 vv = *reinterpret_cast<const float4*>(&g_v[gof]);
                float* dv = &Vs[row * 72 + (cq << 2)];
                dv[0] = f2tf32f(vv.x); dv[1] = f2tf32f(vv.y);
                dv[2] = f2tf32f(vv.z); dv[3] = f2tf32f(vv.w);
            }
            if (t < 64) Ms[t] = mask[b * S_ + kbase + t];
        }
        asm volatile("bar.sync 1, 256;" ::: "memory");  // (B): consumers only

        // dropout words for this tile (produced during iteration kt-1)
        const unsigned* mb = Mb + ((kt & 1) << 8);
        const uint2 dwa = *reinterpret_cast<const uint2*>(&mb[R0 * 2]);
        const uint2 dwb = *reinterpret_cast<const uint2*>(&mb[(R0 + 8) * 2]);

        // ---- S = Q K^T ----
        float sacc[8][4];
        #pragma unroll
        for (int nt = 0; nt < 8; nt++)
            #pragma unroll
            for (int r = 0; r < 4; r++) sacc[nt][r] = 0.0f;

        #pragma unroll
        for (int k8 = 0; k8 < 8; k8++) {
            const int cqa = 2 * k8;
            uint32_t a0 = __float_as_uint(Q0[((cqa ^ sw0) << 2) + qd]);
            uint32_t a1 = __float_as_uint(Q1[((cqa ^ sw1) << 2) + qd]);
            uint32_t a2 = __float_as_uint(Q0[(((cqa + 1) ^ sw0) << 2) + qd]);
            uint32_t a3 = __float_as_uint(Q1[(((cqa + 1) ^ sw1) << 2) + qd]);
            #pragma unroll
            for (int nt = 0; nt < 8; nt++) {
                const int key = (nt << 3) + grp;
                const int ksw = key & 15;
                const float* kr = &Ks[key * 72];
                uint32_t b0 = __float_as_uint(kr[((cqa ^ ksw) << 2) + qd]);
                uint32_t b1 = __float_as_uint(kr[(((cqa + 1) ^ ksw) << 2) + qd]);
                mma_tf32(sacc[nt], a0, a1, a2, a3, b0, b1);
            }
        }

        // ---- mask + scale ----
        #pragma unroll
        for (int nt = 0; nt < 8; nt++) {
            const int col = (nt << 3) + (qd << 1);
            const int mu0 = Ms[col], mu1 = Ms[col + 1];
            sacc[nt][0] = mu0 ? sacc[nt][0] * scale : -INFINITY;
            sacc[nt][1] = mu1 ? sacc[nt][1] * scale : -INFINITY;
            sacc[nt][2] = mu0 ? sacc[nt][2] * scale : -INFINITY;
            sacc[nt][3] = mu1 ? sacc[nt][3] * scale : -INFINITY;
        }

        // ---- row max (quad shuffle) ----
        float mx0 = -INFINITY, mx1 = -INFINITY;
        #pragma unroll
        for (int nt = 0; nt < 8; nt++) {
            mx0 = fmaxf(mx0, fmaxf(sacc[nt][0], sacc[nt][1]));
            mx1 = fmaxf(mx1, fmaxf(sacc[nt][2], sacc[nt][3]));
        }
        #pragma unroll
        for (int o = 1; o < 4; o <<= 1) {
            mx0 = fmaxf(mx0, __shfl_xor_sync(0xffffffffu, mx0, o));
            mx1 = fmaxf(mx1, __shfl_xor_sync(0xffffffffu, mx1, o));
        }
        const float mn0 = fmaxf(mrow0, mx0);
        const float mn1 = fmaxf(mrow1, mx1);
        const float me0 = (mn0 == -INFINITY) ? 0.0f : mn0;
        const float me1 = (mn1 == -INFINITY) ? 0.0f : mn1;
        const float cf0 = (mrow0 == -INFINITY) ? ((mn0 == -INFINITY) ? 1.0f : 0.0f)
                                               : __expf(mrow0 - me0);
        const float cf1 = (mrow1 == -INFINITY) ? ((mn1 == -INFINITY) ? 1.0f : 0.0f)
                                               : __expf(mrow1 - me1);

        // ---- exp, dropout (smem bit lookup), P store ----
        float rs0 = 0.0f, rs1 = 0.0f;
        #pragma unroll
        for (int nt = 0; nt < 8; nt++) {
            const int col = (nt << 3) + (qd << 1);
            const unsigned wa  = (nt < 4) ? dwa.x : dwa.y;
            const unsigned wb2 = (nt < 4) ? dwb.x : dwb.y;
            const int sh = col & 31;
            const float p00 = __expf(sacc[nt][0] - me0);
            const float p01 = __expf(sacc[nt][1] - me0);
            const float p10 = __expf(sacc[nt][2] - me1);
            const float p11 = __expf(sacc[nt][3] - me1);
            rs0 += p00 + p01;
            rs1 += p10 + p11;
            const float d00 = ((wa  >> sh) & 1u)       ? p00 * (1.0f / 0.9f) : 0.0f;
            const float d01 = ((wa  >> (sh + 1)) & 1u) ? p01 * (1.0f / 0.9f) : 0.0f;
            const float d10 = ((wb2 >> sh) & 1u)       ? p10 * (1.0f / 0.9f) : 0.0f;
            const float d11 = ((wb2 >> (sh + 1)) & 1u) ? p11 * (1.0f / 0.9f) : 0.0f;
            const int pcq = (nt << 1) + (qd >> 1);
            const int lo  = (qd & 1) << 1;
            *reinterpret_cast<float2*>(&P0[((pcq ^ sw0) << 2) + lo]) =
                make_float2(f2tf32f(d00), f2tf32f(d01));
            *reinterpret_cast<float2*>(&P1[((pcq ^ sw1) << 2) + lo]) =
                make_float2(f2tf32f(d10), f2tf32f(d11));
        }
        #pragma unroll
        for (int o = 1; o < 4; o <<= 1) {
            rs0 += __shfl_xor_sync(0xffffffffu, rs0, o);
            rs1 += __shfl_xor_sync(0xffffffffu, rs1, o);
        }
        lrow0 = lrow0 * cf0 + rs0;
        lrow1 = lrow1 * cf1 + rs1;
        mrow0 = mn0;
        mrow1 = mn1;
        #pragma unroll
        for (int nt = 0; nt < 8; nt++) {
            oacc[nt][0] *= cf0; oacc[nt][1] *= cf0;
            oacc[nt][2] *= cf1; oacc[nt][3] *= cf1;
        }
        __syncwarp();

        // ---- O += P V ----
        #pragma unroll
        for (int k8 = 0; k8 < 8; k8++) {
            const int cqa = 2 * k8;
            uint32_t a0 = __float_as_uint(P0[((cqa ^ sw0) << 2) + qd]);
            uint32_t a1 = __float_as_uint(P1[((cqa ^ sw1) << 2) + qd]);
            uint32_t a2 = __float_as_uint(P0[(((cqa + 1) ^ sw0) << 2) + qd]);
            uint32_t a3 = __float_as_uint(P1[(((cqa + 1) ^ sw1) << 2) + qd]);
            const float* v0 = &Vs[((k8 << 3) + qd) * 72 + grp];
            #pragma unroll
            for (int nt = 0; nt < 8; nt++) {
                uint32_t b0 = __float_as_uint(v0[nt << 3]);
                uint32_t b1 = __float_as_uint(v0[4 * 72 + (nt << 3)]);
                mma_tf32(oacc[nt], a0, a1, a2, a3, b0, b1);
            }
        }
    }

    // ---- epilogue ----
    const float il0 = 1.0f / lrow0;
    const float il1 = 1.0f / lrow1;
    const size_t g0 = ((size_t)bh * S_ + q0 + R0) * HD_;
    const size_t g1 = ((size_t)bh * S_ + q0 + R0 + 8) * HD_;
    #pragma unroll
    for (int nt = 0; nt < 8; nt++) {
        const int col = (nt << 3) + (qd << 1);
        *reinterpret_cast<float2*>(&out[g0 + col]) =
            make_float2(oacc[nt][0] * il0, oacc[nt][1] * il0);
        *reinterpret_cast<float2*>(&out[g1 + col]) =
            make_float2(oacc[nt][2] * il1, oacc[nt][3] * il1);
    }
}

// ---------------------------------------------------------------------------
extern "C" void kernel_launch(void* const* d_in, const int* in_sizes, int n_in,
                              void* d_out, int out_size) {
    (void)in_sizes; (void)n_in; (void)out_size;
    const float* query = (const float*)d_in[0];
    const float* key   = (const float*)d_in[1];
    const float* value = (const float*)d_in[2];
    const int*   mask  = (const int*)d_in[3];
    const float* invsc = (const float*)d_in[4];
    const float* Wq    = (const float*)d_in[5];
    const float* bq    = (const float*)d_in[6];
    const float* Wk    = (const float*)d_in[7];
    const float* bk    = (const float*)d_in[8];
    const float* Wv    = (const float*)d_in[9];
    const float* bv    = (const float*)d_in[10];
    float*       out   = (float*)d_out;

    float *qp, *kp, *vp;
    cudaGetSymbolAddress((void**)&qp, g_q);
    cudaGetSymbolAddress((void**)&kp, g_k);
    cudaGetSymbolAddress((void**)&vp, g_v);

    dim3 pg(B_ * S_ / 128, D_ / 64);
    proj_mma_kernel<<<pg, 256>>>(query, Wq, bq, qp);
    proj_mma_kernel<<<pg, 256>>>(key,   Wk, bk, kp);
    proj_mma_kernel<<<pg, 256>>>(value, Wv, bv, vp);

    cudaFuncSetAttribute(attn_mma_kernel, cudaFuncAttributeMaxDynamicSharedMemorySize,
                         ATTN_SMEM_BYTES);
    dim3 ag(S_ / 128, B_ * H_);
    attn_mma_kernel<<<ag, 384, ATTN_SMEM_BYTES>>>(mask, invsc, out);
}

// round 9
// speedup vs baseline: 1.4186x; 1.4186x over previous
#include <cuda_runtime.h>
#include <cstdint>
#include <math.h>

// ============================================================================
// AttentionModel: QKV projection + MHA + jax-threefry dropout.
//   B=2, S=2048, D=1024, H=16, HD=64
// Round 9: dropout mask generated IN-REGISTER inside the consumer mainloop
// via warp ballot (tile kt computes tile kt+1's 32 words/warp), filling the
// attention kernel's idle issue slots. No extra warps/blocks/barriers/gmem.
// Projections: 3x tf32-mma GEMM launches (measured 215us in R5).
// ============================================================================

static constexpr int B_ = 2, H_ = 16, S_ = 2048, D_ = 1024, HD_ = 64;

__device__ float g_q[B_ * S_ * D_];
__device__ float g_k[B_ * S_ * D_];
__device__ float g_v[B_ * S_ * D_];

// ---------------------------------------------------------------------------
// tf32 helpers
// ---------------------------------------------------------------------------
__device__ __forceinline__ float f2tf32f(float x) {
    uint32_t r;
    asm("cvt.rna.tf32.f32 %0, %1;" : "=r"(r) : "f"(x));
    return __uint_as_float(r);
}

__device__ __forceinline__ void mma_tf32(float c[4],
                                         uint32_t a0, uint32_t a1, uint32_t a2, uint32_t a3,
                                         uint32_t b0, uint32_t b1) {
    asm volatile(
        "mma.sync.aligned.m16n8k8.row.col.f32.tf32.tf32.f32 "
        "{%0,%1,%2,%3}, {%4,%5,%6,%7}, {%8,%9}, {%0,%1,%2,%3};"
        : "+f"(c[0]), "+f"(c[1]), "+f"(c[2]), "+f"(c[3])
        : "r"(a0), "r"(a1), "r"(a2), "r"(a3), "r"(b0), "r"(b1));
}

// ---------------------------------------------------------------------------
// Threefry-2x32 (JAX partitionable) — verified exact in Round 2.
// keep(idx) <=> bits < 3865470464u (exact integer form of u < 0.9f).
// ---------------------------------------------------------------------------
struct KeyPair { unsigned a, b; };

__host__ __device__ constexpr unsigned rotlc(unsigned x, int r) {
    return (x << r) | (x >> (32 - r));
}

__host__ __device__ constexpr KeyPair threefry_block(unsigned k0, unsigned k1,
                                                     unsigned x0, unsigned x1) {
    unsigned k2 = k0 ^ k1 ^ 0x1BD11BDAu;
    x0 += k0; x1 += k1;
    const int RA[4] = {13, 15, 26, 6};
    const int RB[4] = {17, 29, 16, 24};
    for (int i = 0; i < 4; i++) { x0 += x1; x1 = rotlc(x1, RA[i]); x1 ^= x0; }
    x0 += k1; x1 += k2 + 1u;
    for (int i = 0; i < 4; i++) { x0 += x1; x1 = rotlc(x1, RB[i]); x1 ^= x0; }
    x0 += k2; x1 += k0 + 2u;
    for (int i = 0; i < 4; i++) { x0 += x1; x1 = rotlc(x1, RA[i]); x1 ^= x0; }
    x0 += k0; x1 += k1 + 3u;
    for (int i = 0; i < 4; i++) { x0 += x1; x1 = rotlc(x1, RB[i]); x1 ^= x0; }
    x0 += k1; x1 += k2 + 4u;
    for (int i = 0; i < 4; i++) { x0 += x1; x1 = rotlc(x1, RA[i]); x1 ^= x0; }
    x0 += k2; x1 += k0 + 5u;
    return {x0, x1};
}

__device__ __forceinline__ bool keep_bit(unsigned idx) {
    constexpr KeyPair FK = threefry_block(0u, 0u, 0u, 12345u);
    KeyPair r = threefry_block(FK.a, FK.b, 0u, idx);
    return (r.a ^ r.b) < 3865470464u;
}

// ---------------------------------------------------------------------------
// Projection GEMM (tf32 mma): Y[4096,1024] = X @ W^T + bias (R5 version)
// ---------------------------------------------------------------------------
__global__ void __launch_bounds__(256) proj_mma_kernel(const float* __restrict__ X,
                                                       const float* __restrict__ W,
                                                       const float* __restrict__ bias,
                                                       float* __restrict__ Y) {
    __shared__ float Xs[128 * 36];
    __shared__ float Ws[64 * 36];

    const int m0 = blockIdx.x << 7;
    const int n0 = blockIdx.y << 6;
    const int t  = threadIdx.x;
    const int lane = t & 31, w = t >> 5;
    const int grp = lane >> 2, qd = lane & 3;
    const int wm = w >> 1, wn = w & 1;
    const int frow = t >> 3;
    const int fc4  = (t & 7) << 2;

    float acc[2][4][4];
    #pragma unroll
    for (int mt = 0; mt < 2; mt++)
        #pragma unroll
        for (int nt = 0; nt < 4; nt++)
            #pragma unroll
            for (int r = 0; r < 4; r++) acc[mt][nt][r] = 0.0f;

    const float* xa0 = &Xs[(wm * 32 + grp) * 36 + qd];
    const float* xa1 = &Xs[(wm * 32 + 16 + grp) * 36 + qd];
    const float* wb  = &Ws[(wn * 32 + grp) * 36 + qd];

    for (int k0 = 0; k0 < D_; k0 += 32) {
        __syncthreads();
        #pragma unroll
        for (int l = 0; l < 4; l++) {
            const int row = frow + (l << 5);
            float4 v = *reinterpret_cast<const float4*>(&X[(size_t)(m0 + row) * D_ + k0 + fc4]);
            float* d = &Xs[row * 36 + fc4];
            d[0] = f2tf32f(v.x); d[1] = f2tf32f(v.y); d[2] = f2tf32f(v.z); d[3] = f2tf32f(v.w);
        }
        #pragma unroll
        for (int l = 0; l < 2; l++) {
            const int row = frow + (l << 5);
            float4 v = *reinterpret_cast<const float4*>(&W[(size_t)(n0 + row) * D_ + k0 + fc4]);
            float* d = &Ws[row * 36 + fc4];
            d[0] = f2tf32f(v.x); d[1] = f2tf32f(v.y); d[2] = f2tf32f(v.z); d[3] = f2tf32f(v.w);
        }
        __syncthreads();

        #pragma unroll
        for (int k8 = 0; k8 < 4; k8++) {
            const int kk = k8 << 3;
            uint32_t a[2][4];
            #pragma unroll
            for (int mt = 0; mt < 2; mt++) {
                const float* base = mt ? xa1 : xa0;
                a[mt][0] = __float_as_uint(base[kk]);
                a[mt][1] = __float_as_uint(base[8 * 36 + kk]);
                a[mt][2] = __float_as_uint(base[kk + 4]);
                a[mt][3] = __float_as_uint(base[8 * 36 + kk + 4]);
            }
            #pragma unroll
            for (int nt = 0; nt < 4; nt++) {
                uint32_t b0 = __float_as_uint(wb[nt * 8 * 36 + kk]);
                uint32_t b1 = __float_as_uint(wb[nt * 8 * 36 + kk + 4]);
                mma_tf32(acc[0][nt], a[0][0], a[0][1], a[0][2], a[0][3], b0, b1);
                mma_tf32(acc[1][nt], a[1][0], a[1][1], a[1][2], a[1][3], b0, b1);
            }
        }
    }

    #pragma unroll
    for (int mt = 0; mt < 2; mt++) {
        const int r0 = m0 + wm * 32 + mt * 16 + grp;
        #pragma unroll
        for (int nt = 0; nt < 4; nt++) {
            const int c = n0 + wn * 32 + nt * 8 + (qd << 1);
            const float b0 = bias[c], b1 = bias[c + 1];
            float2 v0 = make_float2(acc[mt][nt][0] + b0, acc[mt][nt][1] + b1);
            float2 v1 = make_float2(acc[mt][nt][2] + b0, acc[mt][nt][3] + b1);
            *reinterpret_cast<float2*>(&Y[(size_t)r0 * D_ + c]) = v0;
            *reinterpret_cast<float2*>(&Y[(size_t)(r0 + 8) * D_ + c]) = v1;
        }
    }
}

// ---------------------------------------------------------------------------
// Flash attention (tf32 mma) with in-register ballot dropout:
// grid (S/128, B*H), 256 thr (8 warps), 2 blocks/SM.
// Warp w owns q-rows [16w,16w+16); per tile it needs 32 mask words, which it
// generates one tile ahead via 32 ballots (lane = bit index).
// smem: Qs[128][72] swz | Ks[64][72] swz | Vs[64][72] plain | Ps[128][72] swz
// ---------------------------------------------------------------------------
static constexpr int ATTN_SMEM_FLOATS = 128 * 72 + 64 * 72 + 64 * 72 + 128 * 72 + 64;
static constexpr int ATTN_SMEM_BYTES  = ATTN_SMEM_FLOATS * 4;

__global__ void __launch_bounds__(256, 2) attn_mma_kernel(const int* __restrict__ mask,
                                                          const float* __restrict__ inv_scale_p,
                                                          float* __restrict__ out) {
    extern __shared__ float sm[];
    float* Qs = sm;                       // 128 x 72, xor-swizzled quads
    float* Ks = Qs + 128 * 72;            // 64 x 72, xor-swizzled
    float* Vs = Ks + 64 * 72;             // 64 x 72, plain
    float* Ps = Vs + 64 * 72;             // 128 x 72, xor-swizzled
    int*   Ms = (int*)(Ps + 128 * 72);    // 64

    const int q0 = blockIdx.x << 7;
    const int bh = blockIdx.y;
    const int b  = bh >> 4;
    const int hcol = (bh & 15) << 6;
    const int t = threadIdx.x;
    const int lane = t & 31, w = t >> 5;
    const int grp = lane >> 2, qd = lane & 3;
    const int R0 = (w << 4) + grp;
    const int sw0 = R0 & 15, sw1 = (R0 + 8) & 15;
    const float scale = 1.0f / inv_scale_p[0];

    float* Q0 = &Qs[R0 * 72];
    float* Q1 = &Qs[(R0 + 8) * 72];
    float* P0 = &Ps[R0 * 72];
    float* P1 = &Ps[(R0 + 8) * 72];

    // global q-row base of this warp's 16 rows (within [B*H*S])
    const unsigned wrow0 = (unsigned)bh * (unsigned)S_ + (unsigned)(q0 + (w << 4));

    // ---- load Q tile (swizzled, tf32) ----
    {
        const int cq = t & 15;
        #pragma unroll
        for (int l = 0; l < 8; l++) {
            const int row = (t >> 4) + (l << 4);
            float4 v = *reinterpret_cast<const float4*>(
                &g_q[(size_t)(b * S_ + q0 + row) * D_ + hcol + (cq << 2)]);
            float* d = &Qs[row * 72 + ((cq ^ (row & 15)) << 2)];
            d[0] = f2tf32f(v.x); d[1] = f2tf32f(v.y); d[2] = f2tf32f(v.z); d[3] = f2tf32f(v.w);
        }
    }

    // ---- generate tile-0 dropout words (32 ballots; lane = bit) ----
    unsigned ca_x, ca_y, cb_x, cb_y;   // current tile: rows R0 (a) and R0+8 (b)
    {
        #pragma unroll 4
        for (int j = 0; j < 32; j++) {
            const int r = j >> 1, h = j & 1;
            const unsigned idx = (wrow0 + (unsigned)r) * (unsigned)S_ +
                                 ((unsigned)h << 5) + (unsigned)lane;
            const unsigned bal = __ballot_sync(0xffffffffu, keep_bit(idx));
            if (r == grp)          { if (h) ca_y = bal; else ca_x = bal; }
            else if (r == grp + 8) { if (h) cb_y = bal; else cb_x = bal; }
        }
    }

    float oacc[8][4];
    #pragma unroll
    for (int nt = 0; nt < 8; nt++)
        #pragma unroll
        for (int r = 0; r < 4; r++) oacc[nt][r] = 0.0f;
    float mrow0 = -INFINITY, mrow1 = -INFINITY;
    float lrow0 = 0.0f, lrow1 = 0.0f;

    for (int kt = 0; kt < S_ / 64; kt++) {
        const int kbase = kt << 6;
        __syncthreads();
        // ---- K/V tile fill ----
        {
            const int cq = t & 15;
            #pragma unroll
            for (int l = 0; l < 4; l++) {
                const int row = (t >> 4) + (l << 4);
                const size_t gof = (size_t)(b * S_ + kbase + row) * D_ + hcol + (cq << 2);
                float4 kv = *reinterpret_cast<const float4*>(&g_k[gof]);
                float* dk = &Ks[row * 72 + ((cq ^ (row & 15)) << 2)];
                dk[0] = f2tf32f(kv.x); dk[1] = f2tf32f(kv.y);
                dk[2] = f2tf32f(kv.z); dk[3] = f2tf32f(kv.w);
                float4 vv = *reinterpret_cast<const float4*>(&g_v[gof]);
                float* dv = &Vs[row * 72 + (cq << 2)];
                dv[0] = f2tf32f(vv.x); dv[1] = f2tf32f(vv.y);
                dv[2] = f2tf32f(vv.z); dv[3] = f2tf32f(vv.w);
            }
            if (t < 64) Ms[t] = mask[b * S_ + kbase + t];
        }
        __syncthreads();

        // ---- S = Q K^T ----
        float sacc[8][4];
        #pragma unroll
        for (int nt = 0; nt < 8; nt++)
            #pragma unroll
            for (int r = 0; r < 4; r++) sacc[nt][r] = 0.0f;

        #pragma unroll
        for (int k8 = 0; k8 < 8; k8++) {
            const int cqa = 2 * k8;
            uint32_t a0 = __float_as_uint(Q0[((cqa ^ sw0) << 2) + qd]);
            uint32_t a1 = __float_as_uint(Q1[((cqa ^ sw1) << 2) + qd]);
            uint32_t a2 = __float_as_uint(Q0[(((cqa + 1) ^ sw0) << 2) + qd]);
            uint32_t a3 = __float_as_uint(Q1[(((cqa + 1) ^ sw1) << 2) + qd]);
            #pragma unroll
            for (int nt = 0; nt < 8; nt++) {
                const int key = (nt << 3) + grp;
                const int ksw = key & 15;
                const float* kr = &Ks[key * 72];
                uint32_t b0 = __float_as_uint(kr[((cqa ^ ksw) << 2) + qd]);
                uint32_t b1 = __float_as_uint(kr[(((cqa + 1) ^ ksw) << 2) + qd]);
                mma_tf32(sacc[nt], a0, a1, a2, a3, b0, b1);
            }
        }

        // ---- generate NEXT tile's dropout words (fills idle issue slots) ----
        unsigned na_x = 0, na_y = 0, nb_x = 0, nb_y = 0;
        if (kt + 1 < S_ / 64) {
            const unsigned cb = (unsigned)((kt + 1) << 6);
            #pragma unroll 4
            for (int j = 0; j < 32; j++) {
                const int r = j >> 1, h = j & 1;
                const unsigned idx = (wrow0 + (unsigned)r) * (unsigned)S_ + cb +
                                     ((unsigned)h << 5) + (unsigned)lane;
                const unsigned bal = __ballot_sync(0xffffffffu, keep_bit(idx));
                if (r == grp)          { if (h) na_y = bal; else na_x = bal; }
                else if (r == grp + 8) { if (h) nb_y = bal; else nb_x = bal; }
            }
        }

        // ---- mask + scale ----
        #pragma unroll
        for (int nt = 0; nt < 8; nt++) {
            const int col = (nt << 3) + (qd << 1);
            const int mu0 = Ms[col], mu1 = Ms[col + 1];
            sacc[nt][0] = mu0 ? sacc[nt][0] * scale : -INFINITY;
            sacc[nt][1] = mu1 ? sacc[nt][1] * scale : -INFINITY;
            sacc[nt][2] = mu0 ? sacc[nt][2] * scale : -INFINITY;
            sacc[nt][3] = mu1 ? sacc[nt][3] * scale : -INFINITY;
        }

        // ---- row max (quad shuffle) ----
        float mx0 = -INFINITY, mx1 = -INFINITY;
        #pragma unroll
        for (int nt = 0; nt < 8; nt++) {
            mx0 = fmaxf(mx0, fmaxf(sacc[nt][0], sacc[nt][1]));
            mx1 = fmaxf(mx1, fmaxf(sacc[nt][2], sacc[nt][3]));
        }
        #pragma unroll
        for (int o = 1; o < 4; o <<= 1) {
            mx0 = fmaxf(mx0, __shfl_xor_sync(0xffffffffu, mx0, o));
            mx1 = fmaxf(mx1, __shfl_xor_sync(0xffffffffu, mx1, o));
        }
        const float mn0 = fmaxf(mrow0, mx0);
        const float mn1 = fmaxf(mrow1, mx1);
        const float me0 = (mn0 == -INFINITY) ? 0.0f : mn0;
        const float me1 = (mn1 == -INFINITY) ? 0.0f : mn1;
        const float cf0 = (mrow0 == -INFINITY) ? ((mn0 == -INFINITY) ? 1.0f : 0.0f)
                                               : __expf(mrow0 - me0);
        const float cf1 = (mrow1 == -INFINITY) ? ((mn1 == -INFINITY) ? 1.0f : 0.0f)
                                               : __expf(mrow1 - me1);

        // ---- exp, dropout (register bit lookup), P store ----
        float rs0 = 0.0f, rs1 = 0.0f;
        #pragma unroll
        for (int nt = 0; nt < 8; nt++) {
            const int col = (nt << 3) + (qd << 1);
            const unsigned wa  = (nt < 4) ? ca_x : ca_y;
            const unsigned wb2 = (nt < 4) ? cb_x : cb_y;
            const int sh = col & 31;
            const float p00 = __expf(sacc[nt][0] - me0);
            const float p01 = __expf(sacc[nt][1] - me0);
            const float p10 = __expf(sacc[nt][2] - me1);
            const float p11 = __expf(sacc[nt][3] - me1);
            rs0 += p00 + p01;
            rs1 += p10 + p11;
            const float d00 = ((wa  >> sh) & 1u)       ? p00 * (1.0f / 0.9f) : 0.0f;
            const float d01 = ((wa  >> (sh + 1)) & 1u) ? p01 * (1.0f / 0.9f) : 0.0f;
            const float d10 = ((wb2 >> sh) & 1u)       ? p10 * (1.0f / 0.9f) : 0.0f;
            const float d11 = ((wb2 >> (sh + 1)) & 1u) ? p11 * (1.0f / 0.9f) : 0.0f;
            const int pcq = (nt << 1) + (qd >> 1);
            const int lo  = (qd & 1) << 1;
            *reinterpret_cast<float2*>(&P0[((pcq ^ sw0) << 2) + lo]) =
                make_float2(f2tf32f(d00), f2tf32f(d01));
            *reinterpret_cast<float2*>(&P1[((pcq ^ sw1) << 2) + lo]) =
                make_float2(f2tf32f(d10), f2tf32f(d11));
        }
        #pragma unroll
        for (int o = 1; o < 4; o <<= 1) {
            rs0 += __shfl_xor_sync(0xffffffffu, rs0, o);
            rs1 += __shfl_xor_sync(0xffffffffu, rs1, o);
        }
        lrow0 = lrow0 * cf0 + rs0;
        lrow1 = lrow1 * cf1 + rs1;
        mrow0 = mn0;
        mrow1 = mn1;
        #pragma unroll
        for (int nt = 0; nt < 8; nt++) {
            oacc[nt][0] *= cf0; oacc[nt][1] *= cf0;
            oacc[nt][2] *= cf1; oacc[nt][3] *= cf1;
        }
        __syncwarp();

        // ---- O += P V ----
        #pragma unroll
        for (int k8 = 0; k8 < 8; k8++) {
            const int cqa = 2 * k8;
            uint32_t a0 = __float_as_uint(P0[((cqa ^ sw0) << 2) + qd]);
            uint32_t a1 = __float_as_uint(P1[((cqa ^ sw1) << 2) + qd]);
            uint32_t a2 = __float_as_uint(P0[(((cqa + 1) ^ sw0) << 2) + qd]);
            uint32_t a3 = __float_as_uint(P1[(((cqa + 1) ^ sw1) << 2) + qd]);
            const float* v0 = &Vs[((k8 << 3) + qd) * 72 + grp];
            #pragma unroll
            for (int nt = 0; nt < 8; nt++) {
                uint32_t b0 = __float_as_uint(v0[nt << 3]);
                uint32_t b1 = __float_as_uint(v0[4 * 72 + (nt << 3)]);
                mma_tf32(oacc[nt], a0, a1, a2, a3, b0, b1);
            }
        }

        // rotate double buffer
        ca_x = na_x; ca_y = na_y; cb_x = nb_x; cb_y = nb_y;
    }

    // ---- epilogue ----
    const float il0 = 1.0f / lrow0;
    const float il1 = 1.0f / lrow1;
    const size_t g0 = ((size_t)bh * S_ + q0 + R0) * HD_;
    const size_t g1 = ((size_t)bh * S_ + q0 + R0 + 8) * HD_;
    #pragma unroll
    for (int nt = 0; nt < 8; nt++) {
        const int col = (nt << 3) + (qd << 1);
        *reinterpret_cast<float2*>(&out[g0 + col]) =
            make_float2(oacc[nt][0] * il0, oacc[nt][1] * il0);
        *reinterpret_cast<float2*>(&out[g1 + col]) =
            make_float2(oacc[nt][2] * il1, oacc[nt][3] * il1);
    }
}

// ---------------------------------------------------------------------------
extern "C" void kernel_launch(void* const* d_in, const int* in_sizes, int n_in,
                              void* d_out, int out_size) {
    (void)in_sizes; (void)n_in; (void)out_size;
    const float* query = (const float*)d_in[0];
    const float* key   = (const float*)d_in[1];
    const float* value = (const float*)d_in[2];
    const int*   mask  = (const int*)d_in[3];
    const float* invsc = (const float*)d_in[4];
    const float* Wq    = (const float*)d_in[5];
    const float* bq    = (const float*)d_in[6];
    const float* Wk    = (const float*)d_in[7];
    const float* bk    = (const float*)d_in[8];
    const float* Wv    = (const float*)d_in[9];
    const float* bv    = (const float*)d_in[10];
    float*       out   = (float*)d_out;

    float *qp, *kp, *vp;
    cudaGetSymbolAddress((void**)&qp, g_q);
    cudaGetSymbolAddress((void**)&kp, g_k);
    cudaGetSymbolAddress((void**)&vp, g_v);

    dim3 pg(B_ * S_ / 128, D_ / 64);
    proj_mma_kernel<<<pg, 256>>>(query, Wq, bq, qp);
    proj_mma_kernel<<<pg, 256>>>(key,   Wk, bk, kp);
    proj_mma_kernel<<<pg, 256>>>(value, Wv, bv, vp);

    cudaFuncSetAttribute(attn_mma_kernel, cudaFuncAttributeMaxDynamicSharedMemorySize,
                         ATTN_SMEM_BYTES);
    dim3 ag(S_ / 128, B_ * H_);
    attn_mma_kernel<<<ag, 256, ATTN_SMEM_BYTES>>>(mask, invsc, out);
}

// round 11
// speedup vs baseline: 1.7028x; 1.2004x over previous
#include <cuda_runtime.h>
#include <cstdint>
#include <math.h>

// ============================================================================
// AttentionModel: QKV projection + MHA + jax-threefry dropout.
//   B=2, S=2048, D=1024, H=16, HD=64
// Round 10: mask-aware compacted dropout generation. attn_mask kills whole
// key columns (p=0 exactly), so keep-bits are only computed for UNMASKED
// columns (~50% -> threefry work halved). Producer stays in-loop (R9
// structure); bits are rank-compacted via warp-0 ballot + smem column list;
// consumer maps column->rank with register popcounts. Consumed bits and all
// numerics identical to R5/R7/R9 (rel_err must stay 4.231e-4).
// ============================================================================

static constexpr int B_ = 2, H_ = 16, S_ = 2048, D_ = 1024, HD_ = 64;

__device__ float g_q[B_ * S_ * D_];
__device__ float g_k[B_ * S_ * D_];
__device__ float g_v[B_ * S_ * D_];

// ---------------------------------------------------------------------------
// tf32 helpers
// ---------------------------------------------------------------------------
__device__ __forceinline__ float f2tf32f(float x) {
    uint32_t r;
    asm("cvt.rna.tf32.f32 %0, %1;" : "=r"(r) : "f"(x));
    return __uint_as_float(r);
}

__device__ __forceinline__ void mma_tf32(float c[4],
                                         uint32_t a0, uint32_t a1, uint32_t a2, uint32_t a3,
                                         uint32_t b0, uint32_t b1) {
    asm volatile(
        "mma.sync.aligned.m16n8k8.row.col.f32.tf32.tf32.f32 "
        "{%0,%1,%2,%3}, {%4,%5,%6,%7}, {%8,%9}, {%0,%1,%2,%3};"
        : "+f"(c[0]), "+f"(c[1]), "+f"(c[2]), "+f"(c[3])
        : "r"(a0), "r"(a1), "r"(a2), "r"(a3), "r"(b0), "r"(b1));
}

// ---------------------------------------------------------------------------
// Threefry-2x32 (JAX partitionable) — verified exact in Round 2.
// keep(idx) <=> bits < 3865470464u (exact integer form of u < 0.9f).
// ---------------------------------------------------------------------------
struct KeyPair { unsigned a, b; };

__host__ __device__ constexpr unsigned rotlc(unsigned x, int r) {
    return (x << r) | (x >> (32 - r));
}

__host__ __device__ constexpr KeyPair threefry_block(unsigned k0, unsigned k1,
                                                     unsigned x0, unsigned x1) {
    unsigned k2 = k0 ^ k1 ^ 0x1BD11BDAu;
    x0 += k0; x1 += k1;
    const int RA[4] = {13, 15, 26, 6};
    const int RB[4] = {17, 29, 16, 24};
    for (int i = 0; i < 4; i++) { x0 += x1; x1 = rotlc(x1, RA[i]); x1 ^= x0; }
    x0 += k1; x1 += k2 + 1u;
    for (int i = 0; i < 4; i++) { x0 += x1; x1 = rotlc(x1, RB[i]); x1 ^= x0; }
    x0 += k2; x1 += k0 + 2u;
    for (int i = 0; i < 4; i++) { x0 += x1; x1 = rotlc(x1, RA[i]); x1 ^= x0; }
    x0 += k0; x1 += k1 + 3u;
    for (int i = 0; i < 4; i++) { x0 += x1; x1 = rotlc(x1, RB[i]); x1 ^= x0; }
    x0 += k1; x1 += k2 + 4u;
    for (int i = 0; i < 4; i++) { x0 += x1; x1 = rotlc(x1, RA[i]); x1 ^= x0; }
    x0 += k2; x1 += k0 + 5u;
    return {x0, x1};
}

__device__ __forceinline__ bool keep_bit(unsigned idx) {
    constexpr KeyPair FK = threefry_block(0u, 0u, 0u, 12345u);
    KeyPair r = threefry_block(FK.a, FK.b, 0u, idx);
    return (r.a ^ r.b) < 3865470464u;
}

// ---------------------------------------------------------------------------
// Rank-compacted dropout-word generation for one 64-col tile.
// Lanes 0..15 handle ranks [0,h) of row (lane&15); lanes 16..31 ranks [h,u).
// Returns rank-indexed words for rows grp and grp+8 (warp-local).
// Warp-collective; all 32 lanes must participate.
// ---------------------------------------------------------------------------
__device__ __forceinline__ void gen_words(int u, const int* __restrict__ Un,
                                          unsigned wrow0, unsigned cbase,
                                          int lane, int grp,
                                          unsigned& a0, unsigned& a1,
                                          unsigned& b0w, unsigned& b1w) {
    const int h = (u + 1) >> 1;
    const int rowL = lane & 15;
    const int halfS = lane >> 4;
    const int myStart = halfS ? h : 0;
    const int myCount = halfS ? (u - h) : h;
    const unsigned base = (wrow0 + (unsigned)rowL) * (unsigned)S_ + cbase;
    unsigned word = 0;
    for (int k = 0; k < h; k += 2) {  // 2 independent hash chains per iter
        const bool p0 = (k < myCount);
        const bool p1 = (k + 1 < myCount);
        const int c0 = p0 ? Un[myStart + k] : 0;
        const int c1 = p1 ? Un[myStart + k + 1] : 0;
        const unsigned bb0 = p0 ? (unsigned)keep_bit(base + (unsigned)c0) : 0u;
        const unsigned bb1 = p1 ? (unsigned)keep_bit(base + (unsigned)c1) : 0u;
        word |= (bb0 << k) | (bb1 << (k + 1));
    }
    const unsigned other = __shfl_xor_sync(0xffffffffu, word, 16);
    // lanes < 16: word = ranks [0,h), other = ranks [h,u)
    const unsigned long long comb =
        (unsigned long long)word | ((unsigned long long)other << h);
    const unsigned w0 = (unsigned)comb;
    const unsigned w1 = (unsigned)(comb >> 32);
    a0  = __shfl_sync(0xffffffffu, w0, grp);
    a1  = __shfl_sync(0xffffffffu, w1, grp);
    b0w = __shfl_sync(0xffffffffu, w0, grp + 8);
    b1w = __shfl_sync(0xffffffffu, w1, grp + 8);
}

// ---------------------------------------------------------------------------
// Projection GEMM (tf32 mma): Y[4096,1024] = X @ W^T + bias (R5 version)
// ---------------------------------------------------------------------------
__global__ void __launch_bounds__(256) proj_mma_kernel(const float* __restrict__ X,
                                                       const float* __restrict__ W,
                                                       const float* __restrict__ bias,
                                                       float* __restrict__ Y) {
    __shared__ float Xs[128 * 36];
    __shared__ float Ws[64 * 36];

    const int m0 = blockIdx.x << 7;
    const int n0 = blockIdx.y << 6;
    const int t  = threadIdx.x;
    const int lane = t & 31, w = t >> 5;
    const int grp = lane >> 2, qd = lane & 3;
    const int wm = w >> 1, wn = w & 1;
    const int frow = t >> 3;
    const int fc4  = (t & 7) << 2;

    float acc[2][4][4];
    #pragma unroll
    for (int mt = 0; mt < 2; mt++)
        #pragma unroll
        for (int nt = 0; nt < 4; nt++)
            #pragma unroll
            for (int r = 0; r < 4; r++) acc[mt][nt][r] = 0.0f;

    const float* xa0 = &Xs[(wm * 32 + grp) * 36 + qd];
    const float* xa1 = &Xs[(wm * 32 + 16 + grp) * 36 + qd];
    const float* wb  = &Ws[(wn * 32 + grp) * 36 + qd];

    for (int k0 = 0; k0 < D_; k0 += 32) {
        __syncthreads();
        #pragma unroll
        for (int l = 0; l < 4; l++) {
            const int row = frow + (l << 5);
            float4 v = *reinterpret_cast<const float4*>(&X[(size_t)(m0 + row) * D_ + k0 + fc4]);
            float* d = &Xs[row * 36 + fc4];
            d[0] = f2tf32f(v.x); d[1] = f2tf32f(v.y); d[2] = f2tf32f(v.z); d[3] = f2tf32f(v.w);
        }
        #pragma unroll
        for (int l = 0; l < 2; l++) {
            const int row = frow + (l << 5);
            float4 v = *reinterpret_cast<const float4*>(&W[(size_t)(n0 + row) * D_ + k0 + fc4]);
            float* d = &Ws[row * 36 + fc4];
            d[0] = f2tf32f(v.x); d[1] = f2tf32f(v.y); d[2] = f2tf32f(v.z); d[3] = f2tf32f(v.w);
        }
        __syncthreads();

        #pragma unroll
        for (int k8 = 0; k8 < 4; k8++) {
            const int kk = k8 << 3;
            uint32_t a[2][4];
            #pragma unroll
            for (int mt = 0; mt < 2; mt++) {
                const float* base = mt ? xa1 : xa0;
                a[mt][0] = __float_as_uint(base[kk]);
                a[mt][1] = __float_as_uint(base[8 * 36 + kk]);
                a[mt][2] = __float_as_uint(base[kk + 4]);
                a[mt][3] = __float_as_uint(base[8 * 36 + kk + 4]);
            }
            #pragma unroll
            for (int nt = 0; nt < 4; nt++) {
                uint32_t b0 = __float_as_uint(wb[nt * 8 * 36 + kk]);
                uint32_t b1 = __float_as_uint(wb[nt * 8 * 36 + kk + 4]);
                mma_tf32(acc[0][nt], a[0][0], a[0][1], a[0][2], a[0][3], b0, b1);
                mma_tf32(acc[1][nt], a[1][0], a[1][1], a[1][2], a[1][3], b0, b1);
            }
        }
    }

    #pragma unroll
    for (int mt = 0; mt < 2; mt++) {
        const int r0 = m0 + wm * 32 + mt * 16 + grp;
        #pragma unroll
        for (int nt = 0; nt < 4; nt++) {
            const int c = n0 + wn * 32 + nt * 8 + (qd << 1);
            const float b0 = bias[c], b1 = bias[c + 1];
            float2 v0 = make_float2(acc[mt][nt][0] + b0, acc[mt][nt][1] + b1);
            float2 v1 = make_float2(acc[mt][nt][2] + b0, acc[mt][nt][3] + b1);
            *reinterpret_cast<float2*>(&Y[(size_t)r0 * D_ + c]) = v0;
            *reinterpret_cast<float2*>(&Y[(size_t)(r0 + 8) * D_ + c]) = v1;
        }
    }
}

// ---------------------------------------------------------------------------
// Flash attention (tf32 mma) + compacted in-loop dropout generation.
// grid (S/128, B*H), 256 thr (8 warps), 2 blocks/SM.
// smem: Qs[128][72] | Ks[64][72] | Vs[64][72] | Ps[128][72] | Binf[2][4] | Un[64]
// ---------------------------------------------------------------------------
static constexpr int ATTN_SMEM_FLOATS = 128 * 72 + 64 * 72 + 64 * 72 + 128 * 72 + 8 + 64;
static constexpr int ATTN_SMEM_BYTES  = ATTN_SMEM_FLOATS * 4;

__global__ void __launch_bounds__(256, 2) attn_mma_kernel(const int* __restrict__ mask,
                                                          const float* __restrict__ inv_scale_p,
                                                          float* __restrict__ out) {
    extern __shared__ float sm[];
    float*    Qs = sm;                         // 128 x 72, xor-swizzled quads
    float*    Ks = Qs + 128 * 72;              // 64 x 72, xor-swizzled
    float*    Vs = Ks + 64 * 72;               // 64 x 72, plain
    float*    Ps = Vs + 64 * 72;               // 128 x 72, xor-swizzled
    unsigned* Binf = (unsigned*)(Ps + 128 * 72);  // [2][4]: b0, b1, u, pad
    int*      Un   = (int*)(Binf + 8);            // [64] unmasked col list (next tile)

    const int q0 = blockIdx.x << 7;
    const int bh = blockIdx.y;
    const int b  = bh >> 4;
    const int hcol = (bh & 15) << 6;
    const int t = threadIdx.x;
    const int lane = t & 31, w = t >> 5;
    const int grp = lane >> 2, qd = lane & 3;
    const int R0 = (w << 4) + grp;
    const int sw0 = R0 & 15, sw1 = (R0 + 8) & 15;
    const float scale = 1.0f / inv_scale_p[0];

    float* Q0 = &Qs[R0 * 72];
    float* Q1 = &Qs[(R0 + 8) * 72];
    float* P0 = &Ps[R0 * 72];
    float* P1 = &Ps[(R0 + 8) * 72];

    // global q-row base of this warp's 16 rows (within [B*H*S])
    const unsigned wrow0 = (unsigned)bh * (unsigned)S_ + (unsigned)(q0 + (w << 4));

    // ---- load Q tile (swizzled, tf32) ----
    {
        const int cq = t & 15;
        #pragma unroll
        for (int l = 0; l < 8; l++) {
            const int row = (t >> 4) + (l << 4);
            float4 v = *reinterpret_cast<const float4*>(
                &g_q[(size_t)(b * S_ + q0 + row) * D_ + hcol + (cq << 2)]);
            float* d = &Qs[row * 72 + ((cq ^ (row & 15)) << 2)];
            d[0] = f2tf32f(v.x); d[1] = f2tf32f(v.y); d[2] = f2tf32f(v.z); d[3] = f2tf32f(v.w);
        }
    }

    // ---- warp 0: tile-0 mask ballot + compaction ----
    if (w == 0) {
        const int v0 = mask[b * S_ + lane];
        const int v1 = mask[b * S_ + 32 + lane];
        const unsigned bl0 = __ballot_sync(0xffffffffu, v0 != 0);
        const unsigned bl1 = __ballot_sync(0xffffffffu, v1 != 0);
        const int c0 = __popc(bl0);
        const int r0 = __popc(bl0 & ((1u << lane) - 1u));
        const int r1 = c0 + __popc(bl1 & ((1u << lane) - 1u));
        if (v0) Un[r0] = lane;
        if (v1) Un[r1] = 32 + lane;
        if (lane == 0) {
            Binf[0] = bl0; Binf[1] = bl1;
            Binf[2] = (unsigned)(c0 + __popc(bl1));
        }
    }
    __syncthreads();

    // ---- tile-0 compacted dropout words ----
    unsigned ra0, ra1, rb0w, rb1w;  // rank words: row R0 (a), row R0+8 (b)
    gen_words((int)Binf[2], Un, wrow0, 0u, lane, grp, ra0, ra1, rb0w, rb1w);

    float oacc[8][4];
    #pragma unroll
    for (int nt = 0; nt < 8; nt++)
        #pragma unroll
        for (int r = 0; r < 4; r++) oacc[nt][r] = 0.0f;
    float mrow0 = -INFINITY, mrow1 = -INFINITY;
    float lrow0 = 0.0f, lrow1 = 0.0f;

    for (int kt = 0; kt < S_ / 64; kt++) {
        const int kbase = kt << 6;
        __syncthreads();
        // ---- K/V tile fill; warp 0 also ballots+compacts NEXT tile's mask ----
        {
            const int cq = t & 15;
            #pragma unroll
            for (int l = 0; l < 4; l++) {
                const int row = (t >> 4) + (l << 4);
                const size_t gof = (size_t)(b * S_ + kbase + row) * D_ + hcol + (cq << 2);
                float4 kv = *reinterpret_cast<const float4*>(&g_k[gof]);
                float* dk = &Ks[row * 72 + ((cq ^ (row & 15)) << 2)];
                dk[0] = f2tf32f(kv.x); dk[1] = f2tf32f(kv.y);
                dk[2] = f2tf32f(kv.z); dk[3] = f2tf32f(kv.w);
                float4 vv = *reinterpret_cast<const float4*>(&g_v[gof]);
                float* dv = &Vs[row * 72 + (cq << 2)];
                dv[0] = f2tf32f(vv.x); dv[1] = f2tf32f(vv.y);
                dv[2] = f2tf32f(vv.z); dv[3] = f2tf32f(vv.w);
            }
            if (w == 0 && kt + 1 < S_ / 64) {
                const int mb = b * S_ + ((kt + 1) << 6);
                const int v0 = mask[mb + lane];
                const int v1 = mask[mb + 32 + lane];
                const unsigned bl0 = __ballot_sync(0xffffffffu, v0 != 0);
                const unsigned bl1 = __ballot_sync(0xffffffffu, v1 != 0);
                const int c0 = __popc(bl0);
                const int r0 = __popc(bl0 & ((1u << lane) - 1u));
                const int r1 = c0 + __popc(bl1 & ((1u << lane) - 1u));
                if (v0) Un[r0] = lane;
                if (v1) Un[r1] = 32 + lane;
                if (lane == 0) {
                    const int bi = ((kt + 1) & 1) << 2;
                    Binf[bi + 0] = bl0; Binf[bi + 1] = bl1;
                    Binf[bi + 2] = (unsigned)(c0 + __popc(bl1));
                }
            }
        }
        __syncthreads();

        // current tile's mask ballots (uniform smem broadcast)
        const int cbi = (kt & 1) << 2;
        const unsigned cbl0 = Binf[cbi + 0];
        const unsigned cbl1 = Binf[cbi + 1];
        const int cu0 = __popc(cbl0);

        // ---- S = Q K^T ----
        float sacc[8][4];
        #pragma unroll
        for (int nt = 0; nt < 8; nt++)
            #pragma unroll
            for (int r = 0; r < 4; r++) sacc[nt][r] = 0.0f;

        #pragma unroll
        for (int k8 = 0; k8 < 8; k8++) {
            const int cqa = 2 * k8;
            uint32_t a0 = __float_as_uint(Q0[((cqa ^ sw0) << 2) + qd]);
            uint32_t a1 = __float_as_uint(Q1[((cqa ^ sw1) << 2) + qd]);
            uint32_t a2 = __float_as_uint(Q0[(((cqa + 1) ^ sw0) << 2) + qd]);
            uint32_t a3 = __float_as_uint(Q1[(((cqa + 1) ^ sw1) << 2) + qd]);
            #pragma unroll
            for (int nt = 0; nt < 8; nt++) {
                const int key = (nt << 3) + grp;
                const int ksw = key & 15;
                const float* kr = &Ks[key * 72];
                uint32_t b0 = __float_as_uint(kr[((cqa ^ ksw) << 2) + qd]);
                uint32_t b1 = __float_as_uint(kr[(((cqa + 1) ^ ksw) << 2) + qd]);
                mma_tf32(sacc[nt], a0, a1, a2, a3, b0, b1);
            }
        }

        // ---- generate NEXT tile's compacted dropout words ----
        unsigned na0 = 0, na1 = 0, nb0w = 0, nb1w = 0;
        if (kt + 1 < S_ / 64) {
            const int nbi = ((kt + 1) & 1) << 2;
            gen_words((int)Binf[nbi + 2], Un, wrow0,
                      (unsigned)((kt + 1) << 6), lane, grp, na0, na1, nb0w, nb1w);
        }

        // ---- mask + scale (bits from current ballot words) ----
        int mus0[8], mus1[8];
        #pragma unroll
        for (int nt = 0; nt < 8; nt++) {
            const int col = (nt << 3) + (qd << 1);
            const unsigned selw = (col < 32) ? cbl0 : cbl1;
            const int cl = col & 31;
            const int mu0 = (int)((selw >> cl) & 1u);
            const int mu1 = (int)((selw >> (cl + 1)) & 1u);
            mus0[nt] = mu0; mus1[nt] = mu1;
            sacc[nt][0] = mu0 ? sacc[nt][0] * scale : -INFINITY;
            sacc[nt][1] = mu1 ? sacc[nt][1] * scale : -INFINITY;
            sacc[nt][2] = mu0 ? sacc[nt][2] * scale : -INFINITY;
            sacc[nt][3] = mu1 ? sacc[nt][3] * scale : -INFINITY;
        }

        // ---- row max (quad shuffle) ----
        float mx0 = -INFINITY, mx1 = -INFINITY;
        #pragma unroll
        for (int nt = 0; nt < 8; nt++) {
            mx0 = fmaxf(mx0, fmaxf(sacc[nt][0], sacc[nt][1]));
            mx1 = fmaxf(mx1, fmaxf(sacc[nt][2], sacc[nt][3]));
        }
        #pragma unroll
        for (int o = 1; o < 4; o <<= 1) {
            mx0 = fmaxf(mx0, __shfl_xor_sync(0xffffffffu, mx0, o));
            mx1 = fmaxf(mx1, __shfl_xor_sync(0xffffffffu, mx1, o));
        }
        const float mn0 = fmaxf(mrow0, mx0);
        const float mn1 = fmaxf(mrow1, mx1);
        const float me0 = (mn0 == -INFINITY) ? 0.0f : mn0;
        const float me1 = (mn1 == -INFINITY) ? 0.0f : mn1;
        const float cf0 = (mrow0 == -INFINITY) ? ((mn0 == -INFINITY) ? 1.0f : 0.0f)
                                               : __expf(mrow0 - me0);
        const float cf1 = (mrow1 == -INFINITY) ? ((mn1 == -INFINITY) ? 1.0f : 0.0f)
                                               : __expf(mrow1 - me1);

        // ---- exp, dropout (rank-indexed register bits), P store ----
        float rs0 = 0.0f, rs1 = 0.0f;
        #pragma unroll
        for (int nt = 0; nt < 8; nt++) {
            const int col = (nt << 3) + (qd << 1);
            const int cl = col & 31;
            const unsigned pmsk = (1u << cl) - 1u;
            const int rank0 = (col < 32) ? __popc(cbl0 & pmsk)
                                         : (cu0 + __popc(cbl1 & pmsk));
            const int rank1 = rank0 + mus0[nt];  // rank(col+1)
            const unsigned wA0 = (rank0 < 32) ? ra0 : ra1;
            const unsigned wA1 = (rank1 < 32) ? ra0 : ra1;
            const unsigned wB0 = (rank0 < 32) ? rb0w : rb1w;
            const unsigned wB1 = (rank1 < 32) ? rb0w : rb1w;
            const unsigned k00 = (wA0 >> (rank0 & 31)) & 1u;
            const unsigned k01 = (wA1 >> (rank1 & 31)) & 1u;
            const unsigned k10 = (wB0 >> (rank0 & 31)) & 1u;
            const unsigned k11 = (wB1 >> (rank1 & 31)) & 1u;
            const float p00 = __expf(sacc[nt][0] - me0);
            const float p01 = __expf(sacc[nt][1] - me0);
            const float p10 = __expf(sacc[nt][2] - me1);
            const float p11 = __expf(sacc[nt][3] - me1);
            rs0 += p00 + p01;
            rs1 += p10 + p11;
            const float d00 = k00 ? p00 * (1.0f / 0.9f) : 0.0f;
            const float d01 = k01 ? p01 * (1.0f / 0.9f) : 0.0f;
            const float d10 = k10 ? p10 * (1.0f / 0.9f) : 0.0f;
            const float d11 = k11 ? p11 * (1.0f / 0.9f) : 0.0f;
            (void)mus1;
            const int pcq = (nt << 1) + (qd >> 1);
            const int lo  = (qd & 1) << 1;
            *reinterpret_cast<float2*>(&P0[((pcq ^ sw0) << 2) + lo]) =
                make_float2(f2tf32f(d00), f2tf32f(d01));
            *reinterpret_cast<float2*>(&P1[((pcq ^ sw1) << 2) + lo]) =
                make_float2(f2tf32f(d10), f2tf32f(d11));
        }
        #pragma unroll
        for (int o = 1; o < 4; o <<= 1) {
            rs0 += __shfl_xor_sync(0xffffffffu, rs0, o);
            rs1 += __shfl_xor_sync(0xffffffffu, rs1, o);
        }
        lrow0 = lrow0 * cf0 + rs0;
        lrow1 = lrow1 * cf1 + rs1;
        mrow0 = mn0;
        mrow1 = mn1;
        #pragma unroll
        for (int nt = 0; nt < 8; nt++) {
            oacc[nt][0] *= cf0; oacc[nt][1] *= cf0;
            oacc[nt][2] *= cf1; oacc[nt][3] *= cf1;
        }
        __syncwarp();

        // ---- O += P V ----
        #pragma unroll
        for (int k8 = 0; k8 < 8; k8++) {
            const int cqa = 2 * k8;
            uint32_t a0 = __float_as_uint(P0[((cqa ^ sw0) << 2) + qd]);
            uint32_t a1 = __float_as_uint(P1[((cqa ^ sw1) << 2) + qd]);
            uint32_t a2 = __float_as_uint(P0[(((cqa + 1) ^ sw0) << 2) + qd]);
            uint32_t a3 = __float_as_uint(P1[(((cqa + 1) ^ sw1) << 2) + qd]);
            const float* v0 = &Vs[((k8 << 3) + qd) * 72 + grp];
            #pragma unroll
            for (int nt = 0; nt < 8; nt++) {
                uint32_t b0 = __float_as_uint(v0[nt << 3]);
                uint32_t b1 = __float_as_uint(v0[4 * 72 + (nt << 3)]);
                mma_tf32(oacc[nt], a0, a1, a2, a3, b0, b1);
            }
        }

        // rotate rank-word double buffer
        ra0 = na0; ra1 = na1; rb0w = nb0w; rb1w = nb1w;
    }

    // ---- epilogue ----
    const float il0 = 1.0f / lrow0;
    const float il1 = 1.0f / lrow1;
    const size_t g0 = ((size_t)bh * S_ + q0 + R0) * HD_;
    const size_t g1 = ((size_t)bh * S_ + q0 + R0 + 8) * HD_;
    #pragma unroll
    for (int nt = 0; nt < 8; nt++) {
        const int col = (nt << 3) + (qd << 1);
        *reinterpret_cast<float2*>(&out[g0 + col]) =
            make_float2(oacc[nt][0] * il0, oacc[nt][1] * il0);
        *reinterpret_cast<float2*>(&out[g1 + col]) =
            make_float2(oacc[nt][2] * il1, oacc[nt][3] * il1);
    }
}

// ---------------------------------------------------------------------------
extern "C" void kernel_launch(void* const* d_in, const int* in_sizes, int n_in,
                              void* d_out, int out_size) {
    (void)in_sizes; (void)n_in; (void)out_size;
    const float* query = (const float*)d_in[0];
    const float* key   = (const float*)d_in[1];
    const float* value = (const float*)d_in[2];
    const int*   mask  = (const int*)d_in[3];
    const float* invsc = (const float*)d_in[4];
    const float* Wq    = (const float*)d_in[5];
    const float* bq    = (const float*)d_in[6];
    const float* Wk    = (const float*)d_in[7];
    const float* bk    = (const float*)d_in[8];
    const float* Wv    = (const float*)d_in[9];
    const float* bv    = (const float*)d_in[10];
    float*       out   = (float*)d_out;

    float *qp, *kp, *vp;
    cudaGetSymbolAddress((void**)&qp, g_q);
    cudaGetSymbolAddress((void**)&kp, g_k);
    cudaGetSymbolAddress((void**)&vp, g_v);

    dim3 pg(B_ * S_ / 128, D_ / 64);
    proj_mma_kernel<<<pg, 256>>>(query, Wq, bq, qp);
    proj_mma_kernel<<<pg, 256>>>(key,   Wk, bk, kp);
    proj_mma_kernel<<<pg, 256>>>(value, Wv, bv, vp);

    cudaFuncSetAttribute(attn_mma_kernel, cudaFuncAttributeMaxDynamicSharedMemorySize,
                         ATTN_SMEM_BYTES);
    dim3 ag(S_ / 128, B_ * H_);
    attn_mma_kernel<<<ag, 256, ATTN_SMEM_BYTES>>>(mask, invsc, out);
}

// round 12
// speedup vs baseline: 1.7170x; 1.0083x over previous
#include <cuda_runtime.h>
#include <cstdint>
#include <math.h>

// ============================================================================
// AttentionModel: QKV projection + MHA + jax-threefry dropout.
//   B=2, S=2048, D=1024, H=16, HD=64
// Round 12:
//   - gen_words: 4 independent threefry chains per iteration (was 2) to
//     break the hash RAW-latency limit seen at issue=59.8%.
//   - single merged projection launch (1536 blocks) instead of 3 launches.
// Everything else identical to R11 (mask-compacted threefry, tf32 mma).
// ============================================================================

static constexpr int B_ = 2, H_ = 16, S_ = 2048, D_ = 1024, HD_ = 64;

__device__ float g_q[B_ * S_ * D_];
__device__ float g_k[B_ * S_ * D_];
__device__ float g_v[B_ * S_ * D_];

// ---------------------------------------------------------------------------
// tf32 helpers
// ---------------------------------------------------------------------------
__device__ __forceinline__ float f2tf32f(float x) {
    uint32_t r;
    asm("cvt.rna.tf32.f32 %0, %1;" : "=r"(r) : "f"(x));
    return __uint_as_float(r);
}

__device__ __forceinline__ void mma_tf32(float c[4],
                                         uint32_t a0, uint32_t a1, uint32_t a2, uint32_t a3,
                                         uint32_t b0, uint32_t b1) {
    asm volatile(
        "mma.sync.aligned.m16n8k8.row.col.f32.tf32.tf32.f32 "
        "{%0,%1,%2,%3}, {%4,%5,%6,%7}, {%8,%9}, {%0,%1,%2,%3};"
        : "+f"(c[0]), "+f"(c[1]), "+f"(c[2]), "+f"(c[3])
        : "r"(a0), "r"(a1), "r"(a2), "r"(a3), "r"(b0), "r"(b1));
}

// ---------------------------------------------------------------------------
// Threefry-2x32 (JAX partitionable) — verified exact in Round 2.
// keep(idx) <=> bits < 3865470464u (exact integer form of u < 0.9f).
// ---------------------------------------------------------------------------
struct KeyPair { unsigned a, b; };

__host__ __device__ constexpr unsigned rotlc(unsigned x, int r) {
    return (x << r) | (x >> (32 - r));
}

__host__ __device__ constexpr KeyPair threefry_block(unsigned k0, unsigned k1,
                                                     unsigned x0, unsigned x1) {
    unsigned k2 = k0 ^ k1 ^ 0x1BD11BDAu;
    x0 += k0; x1 += k1;
    const int RA[4] = {13, 15, 26, 6};
    const int RB[4] = {17, 29, 16, 24};
    for (int i = 0; i < 4; i++) { x0 += x1; x1 = rotlc(x1, RA[i]); x1 ^= x0; }
    x0 += k1; x1 += k2 + 1u;
    for (int i = 0; i < 4; i++) { x0 += x1; x1 = rotlc(x1, RB[i]); x1 ^= x0; }
    x0 += k2; x1 += k0 + 2u;
    for (int i = 0; i < 4; i++) { x0 += x1; x1 = rotlc(x1, RA[i]); x1 ^= x0; }
    x0 += k0; x1 += k1 + 3u;
    for (int i = 0; i < 4; i++) { x0 += x1; x1 = rotlc(x1, RB[i]); x1 ^= x0; }
    x0 += k1; x1 += k2 + 4u;
    for (int i = 0; i < 4; i++) { x0 += x1; x1 = rotlc(x1, RA[i]); x1 ^= x0; }
    x0 += k2; x1 += k0 + 5u;
    return {x0, x1};
}

__device__ __forceinline__ bool keep_bit(unsigned idx) {
    constexpr KeyPair FK = threefry_block(0u, 0u, 0u, 12345u);
    KeyPair r = threefry_block(FK.a, FK.b, 0u, idx);
    return (r.a ^ r.b) < 3865470464u;
}

// ---------------------------------------------------------------------------
// Rank-compacted dropout-word generation, 4 hash chains per iteration.
// Lanes 0..15 handle ranks [0,h) of row (lane&15); lanes 16..31 ranks [h,u).
// Warp-collective.
// ---------------------------------------------------------------------------
__device__ __forceinline__ void gen_words(int u, const int* __restrict__ Un,
                                          unsigned wrow0, unsigned cbase,
                                          int lane, int grp,
                                          unsigned& a0, unsigned& a1,
                                          unsigned& b0w, unsigned& b1w) {
    const int h = (u + 1) >> 1;
    const int rowL = lane & 15;
    const int halfS = lane >> 4;
    const int myStart = halfS ? h : 0;
    const int myCount = halfS ? (u - h) : h;
    const unsigned base = (wrow0 + (unsigned)rowL) * (unsigned)S_ + cbase;
    unsigned word = 0;
    for (int k = 0; k < h; k += 4) {
        const int c0 = (k     < myCount) ? Un[myStart + k]     : 0;
        const int c1 = (k + 1 < myCount) ? Un[myStart + k + 1] : 0;
        const int c2 = (k + 2 < myCount) ? Un[myStart + k + 2] : 0;
        const int c3 = (k + 3 < myCount) ? Un[myStart + k + 3] : 0;
        // 4 independent threefry chains — ILP against the 4-cyc alu latency
        const unsigned bb0 = (unsigned)keep_bit(base + (unsigned)c0);
        const unsigned bb1 = (unsigned)keep_bit(base + (unsigned)c1);
        const unsigned bb2 = (unsigned)keep_bit(base + (unsigned)c2);
        const unsigned bb3 = (unsigned)keep_bit(base + (unsigned)c3);
        unsigned nib = bb0 | (bb1 << 1) | (bb2 << 2) | (bb3 << 3);
        const int rem = myCount - k;
        if (rem < 4) nib &= (rem <= 0) ? 0u : ((1u << rem) - 1u);
        word |= nib << k;
    }
    const unsigned other = __shfl_xor_sync(0xffffffffu, word, 16);
    // lanes < 16: word = ranks [0,h), other = ranks [h,u)
    const unsigned long long comb =
        (unsigned long long)word | ((unsigned long long)other << h);
    const unsigned w0 = (unsigned)comb;
    const unsigned w1 = (unsigned)(comb >> 32);
    a0  = __shfl_sync(0xffffffffu, w0, grp);
    a1  = __shfl_sync(0xffffffffu, w1, grp);
    b0w = __shfl_sync(0xffffffffu, w0, grp + 8);
    b1w = __shfl_sync(0xffffffffu, w1, grp + 8);
}

// ---------------------------------------------------------------------------
// Merged projection GEMM (tf32 mma): all three Y = X @ W^T + bias in one
// launch. Grid 1536: rsel = bx>>9 picks {Q,K,V}; g = bx&511 picks the tile.
// ---------------------------------------------------------------------------
__global__ void __launch_bounds__(256) proj3_kernel(
    const float* __restrict__ Xq, const float* __restrict__ Xk, const float* __restrict__ Xv,
    const float* __restrict__ Wq, const float* __restrict__ Wk, const float* __restrict__ Wv,
    const float* __restrict__ bq, const float* __restrict__ bk, const float* __restrict__ bv) {
    __shared__ float Xs[128 * 36];
    __shared__ float Ws[64 * 36];

    const int bx = blockIdx.x;
    const int rsel = bx >> 9;
    const int g = bx & 511;
    const float* X    = (rsel == 0) ? Xq : (rsel == 1) ? Xk : Xv;
    const float* W    = (rsel == 0) ? Wq : (rsel == 1) ? Wk : Wv;
    const float* bias = (rsel == 0) ? bq : (rsel == 1) ? bk : bv;
    float*       Y    = (rsel == 0) ? g_q : (rsel == 1) ? g_k : g_v;

    const int m0 = (g & 31) << 7;
    const int n0 = (g >> 5) << 6;
    const int t  = threadIdx.x;
    const int lane = t & 31, w = t >> 5;
    const int grp = lane >> 2, qd = lane & 3;
    const int wm = w >> 1, wn = w & 1;
    const int frow = t >> 3;
    const int fc4  = (t & 7) << 2;

    float acc[2][4][4];
    #pragma unroll
    for (int mt = 0; mt < 2; mt++)
        #pragma unroll
        for (int nt = 0; nt < 4; nt++)
            #pragma unroll
            for (int r = 0; r < 4; r++) acc[mt][nt][r] = 0.0f;

    const float* xa0 = &Xs[(wm * 32 + grp) * 36 + qd];
    const float* xa1 = &Xs[(wm * 32 + 16 + grp) * 36 + qd];
    const float* wb  = &Ws[(wn * 32 + grp) * 36 + qd];

    for (int k0 = 0; k0 < D_; k0 += 32) {
        __syncthreads();
        #pragma unroll
        for (int l = 0; l < 4; l++) {
            const int row = frow + (l << 5);
            float4 v = *reinterpret_cast<const float4*>(&X[(size_t)(m0 + row) * D_ + k0 + fc4]);
            float* d = &Xs[row * 36 + fc4];
            d[0] = f2tf32f(v.x); d[1] = f2tf32f(v.y); d[2] = f2tf32f(v.z); d[3] = f2tf32f(v.w);
        }
        #pragma unroll
        for (int l = 0; l < 2; l++) {
            const int row = frow + (l << 5);
            float4 v = *reinterpret_cast<const float4*>(&W[(size_t)(n0 + row) * D_ + k0 + fc4]);
            float* d = &Ws[row * 36 + fc4];
            d[0] = f2tf32f(v.x); d[1] = f2tf32f(v.y); d[2] = f2tf32f(v.z); d[3] = f2tf32f(v.w);
        }
        __syncthreads();

        #pragma unroll
        for (int k8 = 0; k8 < 4; k8++) {
            const int kk = k8 << 3;
            uint32_t a[2][4];
            #pragma unroll
            for (int mt = 0; mt < 2; mt++) {
                const float* base = mt ? xa1 : xa0;
                a[mt][0] = __float_as_uint(base[kk]);
                a[mt][1] = __float_as_uint(base[8 * 36 + kk]);
                a[mt][2] = __float_as_uint(base[kk + 4]);
                a[mt][3] = __float_as_uint(base[8 * 36 + kk + 4]);
            }
            #pragma unroll
            for (int nt = 0; nt < 4; nt++) {
                uint32_t b0 = __float_as_uint(wb[nt * 8 * 36 + kk]);
                uint32_t b1 = __float_as_uint(wb[nt * 8 * 36 + kk + 4]);
                mma_tf32(acc[0][nt], a[0][0], a[0][1], a[0][2], a[0][3], b0, b1);
                mma_tf32(acc[1][nt], a[1][0], a[1][1], a[1][2], a[1][3], b0, b1);
            }
        }
    }

    #pragma unroll
    for (int mt = 0; mt < 2; mt++) {
        const int r0 = m0 + wm * 32 + mt * 16 + grp;
        #pragma unroll
        for (int nt = 0; nt < 4; nt++) {
            const int c = n0 + wn * 32 + nt * 8 + (qd << 1);
            const float b0 = bias[c], b1 = bias[c + 1];
            float2 v0 = make_float2(acc[mt][nt][0] + b0, acc[mt][nt][1] + b1);
            float2 v1 = make_float2(acc[mt][nt][2] + b0, acc[mt][nt][3] + b1);
            *reinterpret_cast<float2*>(&Y[(size_t)r0 * D_ + c]) = v0;
            *reinterpret_cast<float2*>(&Y[(size_t)(r0 + 8) * D_ + c]) = v1;
        }
    }
}

// ---------------------------------------------------------------------------
// Flash attention (tf32 mma) + compacted in-loop dropout generation.
// grid (S/128, B*H), 256 thr (8 warps), 2 blocks/SM.
// smem: Qs[128][72] | Ks[64][72] | Vs[64][72] | Ps[128][72] | Binf[2][4] | Un[64]
// ---------------------------------------------------------------------------
static constexpr int ATTN_SMEM_FLOATS = 128 * 72 + 64 * 72 + 64 * 72 + 128 * 72 + 8 + 64;
static constexpr int ATTN_SMEM_BYTES  = ATTN_SMEM_FLOATS * 4;

__global__ void __launch_bounds__(256, 2) attn_mma_kernel(const int* __restrict__ mask,
                                                          const float* __restrict__ inv_scale_p,
                                                          float* __restrict__ out) {
    extern __shared__ float sm[];
    float*    Qs = sm;                         // 128 x 72, xor-swizzled quads
    float*    Ks = Qs + 128 * 72;              // 64 x 72, xor-swizzled
    float*    Vs = Ks + 64 * 72;               // 64 x 72, plain
    float*    Ps = Vs + 64 * 72;               // 128 x 72, xor-swizzled
    unsigned* Binf = (unsigned*)(Ps + 128 * 72);  // [2][4]: b0, b1, u, pad
    int*      Un   = (int*)(Binf + 8);            // [64] unmasked col list (next tile)

    const int q0 = blockIdx.x << 7;
    const int bh = blockIdx.y;
    const int b  = bh >> 4;
    const int hcol = (bh & 15) << 6;
    const int t = threadIdx.x;
    const int lane = t & 31, w = t >> 5;
    const int grp = lane >> 2, qd = lane & 3;
    const int R0 = (w << 4) + grp;
    const int sw0 = R0 & 15, sw1 = (R0 + 8) & 15;
    const float scale = 1.0f / inv_scale_p[0];

    float* Q0 = &Qs[R0 * 72];
    float* Q1 = &Qs[(R0 + 8) * 72];
    float* P0 = &Ps[R0 * 72];
    float* P1 = &Ps[(R0 + 8) * 72];

    // global q-row base of this warp's 16 rows (within [B*H*S])
    const unsigned wrow0 = (unsigned)bh * (unsigned)S_ + (unsigned)(q0 + (w << 4));

    // ---- load Q tile (swizzled, tf32) ----
    {
        const int cq = t & 15;
        #pragma unroll
        for (int l = 0; l < 8; l++) {
            const int row = (t >> 4) + (l << 4);
            float4 v = *reinterpret_cast<const float4*>(
                &g_q[(size_t)(b * S_ + q0 + row) * D_ + hcol + (cq << 2)]);
            float* d = &Qs[row * 72 + ((cq ^ (row & 15)) << 2)];
            d[0] = f2tf32f(v.x); d[1] = f2tf32f(v.y); d[2] = f2tf32f(v.z); d[3] = f2tf32f(v.w);
        }
    }

    // ---- warp 0: tile-0 mask ballot + compaction ----
    if (w == 0) {
        const int v0 = mask[b * S_ + lane];
        const int v1 = mask[b * S_ + 32 + lane];
        const unsigned bl0 = __ballot_sync(0xffffffffu, v0 != 0);
        const unsigned bl1 = __ballot_sync(0xffffffffu, v1 != 0);
        const int c0 = __popc(bl0);
        const int r0 = __popc(bl0 & ((1u << lane) - 1u));
        const int r1 = c0 + __popc(bl1 & ((1u << lane) - 1u));
        if (v0) Un[r0] = lane;
        if (v1) Un[r1] = 32 + lane;
        if (lane == 0) {
            Binf[0] = bl0; Binf[1] = bl1;
            Binf[2] = (unsigned)(c0 + __popc(bl1));
        }
    }
    __syncthreads();

    // ---- tile-0 compacted dropout words ----
    unsigned ra0, ra1, rb0w, rb1w;  // rank words: row R0 (a), row R0+8 (b)
    gen_words((int)Binf[2], Un, wrow0, 0u, lane, grp, ra0, ra1, rb0w, rb1w);

    float oacc[8][4];
    #pragma unroll
    for (int nt = 0; nt < 8; nt++)
        #pragma unroll
        for (int r = 0; r < 4; r++) oacc[nt][r] = 0.0f;
    float mrow0 = -INFINITY, mrow1 = -INFINITY;
    float lrow0 = 0.0f, lrow1 = 0.0f;

    for (int kt = 0; kt < S_ / 64; kt++) {
        const int kbase = kt << 6;
        __syncthreads();
        // ---- K/V tile fill; warp 0 also ballots+compacts NEXT tile's mask ----
        {
            const int cq = t & 15;
            #pragma unroll
            for (int l = 0; l < 4; l++) {
                const int row = (t >> 4) + (l << 4);
                const size_t gof = (size_t)(b * S_ + kbase + row) * D_ + hcol + (cq << 2);
                float4 kv = *reinterpret_cast<const float4*>(&g_k[gof]);
                float* dk = &Ks[row * 72 + ((cq ^ (row & 15)) << 2)];
                dk[0] = f2tf32f(kv.x); dk[1] = f2tf32f(kv.y);
                dk[2] = f2tf32f(kv.z); dk[3] = f2tf32f(kv.w);
                float4 vv = *reinterpret_cast<const float4*>(&g_v[gof]);
                float* dv = &Vs[row * 72 + (cq << 2)];
                dv[0] = f2tf32f(vv.x); dv[1] = f2tf32f(vv.y);
                dv[2] = f2tf32f(vv.z); dv[3] = f2tf32f(vv.w);
            }
            if (w == 0 && kt + 1 < S_ / 64) {
                const int mb = b * S_ + ((kt + 1) << 6);
                const int v0 = mask[mb + lane];
                const int v1 = mask[mb + 32 + lane];
                const unsigned bl0 = __ballot_sync(0xffffffffu, v0 != 0);
                const unsigned bl1 = __ballot_sync(0xffffffffu, v1 != 0);
                const int c0 = __popc(bl0);
                const int r0 = __popc(bl0 & ((1u << lane) - 1u));
                const int r1 = c0 + __popc(bl1 & ((1u << lane) - 1u));
                if (v0) Un[r0] = lane;
                if (v1) Un[r1] = 32 + lane;
                if (lane == 0) {
                    const int bi = ((kt + 1) & 1) << 2;
                    Binf[bi + 0] = bl0; Binf[bi + 1] = bl1;
                    Binf[bi + 2] = (unsigned)(c0 + __popc(bl1));
                }
            }
        }
        __syncthreads();

        // current tile's mask ballots (uniform smem broadcast)
        const int cbi = (kt & 1) << 2;
        const unsigned cbl0 = Binf[cbi + 0];
        const unsigned cbl1 = Binf[cbi + 1];
        const int cu0 = __popc(cbl0);

        // ---- S = Q K^T ----
        float sacc[8][4];
        #pragma unroll
        for (int nt = 0; nt < 8; nt++)
            #pragma unroll
            for (int r = 0; r < 4; r++) sacc[nt][r] = 0.0f;

        #pragma unroll
        for (int k8 = 0; k8 < 8; k8++) {
            const int cqa = 2 * k8;
            uint32_t a0 = __float_as_uint(Q0[((cqa ^ sw0) << 2) + qd]);
            uint32_t a1 = __float_as_uint(Q1[((cqa ^ sw1) << 2) + qd]);
            uint32_t a2 = __float_as_uint(Q0[(((cqa + 1) ^ sw0) << 2) + qd]);
            uint32_t a3 = __float_as_uint(Q1[(((cqa + 1) ^ sw1) << 2) + qd]);
            #pragma unroll
            for (int nt = 0; nt < 8; nt++) {
                const int key = (nt << 3) + grp;
                const int ksw = key & 15;
                const float* kr = &Ks[key * 72];
                uint32_t b0 = __float_as_uint(kr[((cqa ^ ksw) << 2) + qd]);
                uint32_t b1 = __float_as_uint(kr[(((cqa + 1) ^ ksw) << 2) + qd]);
                mma_tf32(sacc[nt], a0, a1, a2, a3, b0, b1);
            }
        }

        // ---- generate NEXT tile's compacted dropout words ----
        unsigned na0 = 0, na1 = 0, nb0w = 0, nb1w = 0;
        if (kt + 1 < S_ / 64) {
            const int nbi = ((kt + 1) & 1) << 2;
            gen_words((int)Binf[nbi + 2], Un, wrow0,
                      (unsigned)((kt + 1) << 6), lane, grp, na0, na1, nb0w, nb1w);
        }

        // ---- mask + scale (bits from current ballot words) ----
        int mus0[8];
        #pragma unroll
        for (int nt = 0; nt < 8; nt++) {
            const int col = (nt << 3) + (qd << 1);
            const unsigned selw = (col < 32) ? cbl0 : cbl1;
            const int cl = col & 31;
            const int mu0 = (int)((selw >> cl) & 1u);
            const int mu1 = (int)((selw >> (cl + 1)) & 1u);
            mus0[nt] = mu0;
            sacc[nt][0] = mu0 ? sacc[nt][0] * scale : -INFINITY;
            sacc[nt][1] = mu1 ? sacc[nt][1] * scale : -INFINITY;
            sacc[nt][2] = mu0 ? sacc[nt][2] * scale : -INFINITY;
            sacc[nt][3] = mu1 ? sacc[nt][3] * scale : -INFINITY;
        }

        // ---- row max (quad shuffle) ----
        float mx0 = -INFINITY, mx1 = -INFINITY;
        #pragma unroll
        for (int nt = 0; nt < 8; nt++) {
            mx0 = fmaxf(mx0, fmaxf(sacc[nt][0], sacc[nt][1]));
            mx1 = fmaxf(mx1, fmaxf(sacc[nt][2], sacc[nt][3]));
        }
        #pragma unroll
        for (int o = 1; o < 4; o <<= 1) {
            mx0 = fmaxf(mx0, __shfl_xor_sync(0xffffffffu, mx0, o));
            mx1 = fmaxf(mx1, __shfl_xor_sync(0xffffffffu, mx1, o));
        }
        const float mn0 = fmaxf(mrow0, mx0);
        const float mn1 = fmaxf(mrow1, mx1);
        const float me0 = (mn0 == -INFINITY) ? 0.0f : mn0;
        const float me1 = (mn1 == -INFINITY) ? 0.0f : mn1;
        const float cf0 = (mrow0 == -INFINITY) ? ((mn0 == -INFINITY) ? 1.0f : 0.0f)
                                               : __expf(mrow0 - me0);
        const float cf1 = (mrow1 == -INFINITY) ? ((mn1 == -INFINITY) ? 1.0f : 0.0f)
                                               : __expf(mrow1 - me1);

        // ---- exp, dropout (rank-indexed register bits), P store ----
        float rs0 = 0.0f, rs1 = 0.0f;
        #pragma unroll
        for (int nt = 0; nt < 8; nt++) {
            const int col = (nt << 3) + (qd << 1);
            const int cl = col & 31;
            const unsigned pmsk = (1u << cl) - 1u;
            const int rank0 = (col < 32) ? __popc(cbl0 & pmsk)
                                         : (cu0 + __popc(cbl1 & pmsk));
            const int rank1 = rank0 + mus0[nt];  // rank(col+1)
            const unsigned wA0 = (rank0 < 32) ? ra0 : ra1;
            const unsigned wA1 = (rank1 < 32) ? ra0 : ra1;
            const unsigned wB0 = (rank0 < 32) ? rb0w : rb1w;
            const unsigned wB1 = (rank1 < 32) ? rb0w : rb1w;
            const unsigned k00 = (wA0 >> (rank0 & 31)) & 1u;
            const unsigned k01 = (wA1 >> (rank1 & 31)) & 1u;
            const unsigned k10 = (wB0 >> (rank0 & 31)) & 1u;
            const unsigned k11 = (wB1 >> (rank1 & 31)) & 1u;
            const float p00 = __expf(sacc[nt][0] - me0);
            const float p01 = __expf(sacc[nt][1] - me0);
            const float p10 = __expf(sacc[nt][2] - me1);
            const float p11 = __expf(sacc[nt][3] - me1);
            rs0 += p00 + p01;
            rs1 += p10 + p11;
            const float d00 = k00 ? p00 * (1.0f / 0.9f) : 0.0f;
            const float d01 = k01 ? p01 * (1.0f / 0.9f) : 0.0f;
            const float d10 = k10 ? p10 * (1.0f / 0.9f) : 0.0f;
            const float d11 = k11 ? p11 * (1.0f / 0.9f) : 0.0f;
            const int pcq = (nt << 1) + (qd >> 1);
            const int lo  = (qd & 1) << 1;
            *reinterpret_cast<float2*>(&P0[((pcq ^ sw0) << 2) + lo]) =
                make_float2(f2tf32f(d00), f2tf32f(d01));
            *reinterpret_cast<float2*>(&P1[((pcq ^ sw1) << 2) + lo]) =
                make_float2(f2tf32f(d10), f2tf32f(d11));
        }
        #pragma unroll
        for (int o = 1; o < 4; o <<= 1) {
            rs0 += __shfl_xor_sync(0xffffffffu, rs0, o);
            rs1 += __shfl_xor_sync(0xffffffffu, rs1, o);
        }
        lrow0 = lrow0 * cf0 + rs0;
        lrow1 = lrow1 * cf1 + rs1;
        mrow0 = mn0;
        mrow1 = mn1;
        #pragma unroll
        for (int nt = 0; nt < 8; nt++) {
            oacc[nt][0] *= cf0; oacc[nt][1] *= cf0;
            oacc[nt][2] *= cf1; oacc[nt][3] *= cf1;
        }
        __syncwarp();

        // ---- O += P V ----
        #pragma unroll
        for (int k8 = 0; k8 < 8; k8++) {
            const int cqa = 2 * k8;
            uint32_t a0 = __float_as_uint(P0[((cqa ^ sw0) << 2) + qd]);
            uint32_t a1 = __float_as_uint(P1[((cqa ^ sw1) << 2) + qd]);
            uint32_t a2 = __float_as_uint(P0[(((cqa + 1) ^ sw0) << 2) + qd]);
            uint32_t a3 = __float_as_uint(P1[(((cqa + 1) ^ sw1) << 2) + qd]);
            const float* v0 = &Vs[((k8 << 3) + qd) * 72 + grp];
            #pragma unroll
            for (int nt = 0; nt < 8; nt++) {
                uint32_t b0 = __float_as_uint(v0[nt << 3]);
                uint32_t b1 = __float_as_uint(v0[4 * 72 + (nt << 3)]);
                mma_tf32(oacc[nt], a0, a1, a2, a3, b0, b1);
            }
        }

        // rotate rank-word double buffer
        ra0 = na0; ra1 = na1; rb0w = nb0w; rb1w = nb1w;
    }

    // ---- epilogue ----
    const float il0 = 1.0f / lrow0;
    const float il1 = 1.0f / lrow1;
    const size_t g0 = ((size_t)bh * S_ + q0 + R0) * HD_;
    const size_t g1 = ((size_t)bh * S_ + q0 + R0 + 8) * HD_;
    #pragma unroll
    for (int nt = 0; nt < 8; nt++) {
        const int col = (nt << 3) + (qd << 1);
        *reinterpret_cast<float2*>(&out[g0 + col]) =
            make_float2(oacc[nt][0] * il0, oacc[nt][1] * il0);
        *reinterpret_cast<float2*>(&out[g1 + col]) =
            make_float2(oacc[nt][2] * il1, oacc[nt][3] * il1);
    }
}

// ---------------------------------------------------------------------------
extern "C" void kernel_launch(void* const* d_in, const int* in_sizes, int n_in,
                              void* d_out, int out_size) {
    (void)in_sizes; (void)n_in; (void)out_size;
    const float* query = (const float*)d_in[0];
    const float* key   = (const float*)d_in[1];
    const float* value = (const float*)d_in[2];
    const int*   mask  = (const int*)d_in[3];
    const float* invsc = (const float*)d_in[4];
    const float* Wq    = (const float*)d_in[5];
    const float* bq    = (const float*)d_in[6];
    const float* Wk    = (const float*)d_in[7];
    const float* bk    = (const float*)d_in[8];
    const float* Wv    = (const float*)d_in[9];
    const float* bv    = (const float*)d_in[10];
    float*       out   = (float*)d_out;

    proj3_kernel<<<1536, 256>>>(query, key, value, Wq, Wk, Wv, bq, bk, bv);

    cudaFuncSetAttribute(attn_mma_kernel, cudaFuncAttributeMaxDynamicSharedMemorySize,
                         ATTN_SMEM_BYTES);
    dim3 ag(S_ / 128, B_ * H_);
    attn_mma_kernel<<<ag, 256, ATTN_SMEM_BYTES>>>(mask, invsc, out);
}

// round 13
// speedup vs baseline: 1.7486x; 1.0184x over previous
#include <cuda_runtime.h>
#include <cstdint>
#include <math.h>

// ============================================================================
// AttentionModel: QKV projection + MHA + jax-threefry dropout.
//   B=2, S=2048, D=1024, H=16, HD=64
// Round 13: double-buffered projection GEMM (register prefetch, one sync per
// K-chunk, 2x smem buffers) — hides LDG latency behind tensor work.
// Attention kernel identical to R12 (mask-compacted threefry, tf32 mma).
// ============================================================================

static constexpr int B_ = 2, H_ = 16, S_ = 2048, D_ = 1024, HD_ = 64;

__device__ float g_q[B_ * S_ * D_];
__device__ float g_k[B_ * S_ * D_];
__device__ float g_v[B_ * S_ * D_];

// ---------------------------------------------------------------------------
// tf32 helpers
// ---------------------------------------------------------------------------
__device__ __forceinline__ float f2tf32f(float x) {
    uint32_t r;
    asm("cvt.rna.tf32.f32 %0, %1;" : "=r"(r) : "f"(x));
    return __uint_as_float(r);
}

__device__ __forceinline__ void mma_tf32(float c[4],
                                         uint32_t a0, uint32_t a1, uint32_t a2, uint32_t a3,
                                         uint32_t b0, uint32_t b1) {
    asm volatile(
        "mma.sync.aligned.m16n8k8.row.col.f32.tf32.tf32.f32 "
        "{%0,%1,%2,%3}, {%4,%5,%6,%7}, {%8,%9}, {%0,%1,%2,%3};"
        : "+f"(c[0]), "+f"(c[1]), "+f"(c[2]), "+f"(c[3])
        : "r"(a0), "r"(a1), "r"(a2), "r"(a3), "r"(b0), "r"(b1));
}

// ---------------------------------------------------------------------------
// Threefry-2x32 (JAX partitionable) — verified exact in Round 2.
// keep(idx) <=> bits < 3865470464u (exact integer form of u < 0.9f).
// ---------------------------------------------------------------------------
struct KeyPair { unsigned a, b; };

__host__ __device__ constexpr unsigned rotlc(unsigned x, int r) {
    return (x << r) | (x >> (32 - r));
}

__host__ __device__ constexpr KeyPair threefry_block(unsigned k0, unsigned k1,
                                                     unsigned x0, unsigned x1) {
    unsigned k2 = k0 ^ k1 ^ 0x1BD11BDAu;
    x0 += k0; x1 += k1;
    const int RA[4] = {13, 15, 26, 6};
    const int RB[4] = {17, 29, 16, 24};
    for (int i = 0; i < 4; i++) { x0 += x1; x1 = rotlc(x1, RA[i]); x1 ^= x0; }
    x0 += k1; x1 += k2 + 1u;
    for (int i = 0; i < 4; i++) { x0 += x1; x1 = rotlc(x1, RB[i]); x1 ^= x0; }
    x0 += k2; x1 += k0 + 2u;
    for (int i = 0; i < 4; i++) { x0 += x1; x1 = rotlc(x1, RA[i]); x1 ^= x0; }
    x0 += k0; x1 += k1 + 3u;
    for (int i = 0; i < 4; i++) { x0 += x1; x1 = rotlc(x1, RB[i]); x1 ^= x0; }
    x0 += k1; x1 += k2 + 4u;
    for (int i = 0; i < 4; i++) { x0 += x1; x1 = rotlc(x1, RA[i]); x1 ^= x0; }
    x0 += k2; x1 += k0 + 5u;
    return {x0, x1};
}

__device__ __forceinline__ bool keep_bit(unsigned idx) {
    constexpr KeyPair FK = threefry_block(0u, 0u, 0u, 12345u);
    KeyPair r = threefry_block(FK.a, FK.b, 0u, idx);
    return (r.a ^ r.b) < 3865470464u;
}

// ---------------------------------------------------------------------------
// Rank-compacted dropout-word generation, 4 hash chains per iteration.
// ---------------------------------------------------------------------------
__device__ __forceinline__ void gen_words(int u, const int* __restrict__ Un,
                                          unsigned wrow0, unsigned cbase,
                                          int lane, int grp,
                                          unsigned& a0, unsigned& a1,
                                          unsigned& b0w, unsigned& b1w) {
    const int h = (u + 1) >> 1;
    const int rowL = lane & 15;
    const int halfS = lane >> 4;
    const int myStart = halfS ? h : 0;
    const int myCount = halfS ? (u - h) : h;
    const unsigned base = (wrow0 + (unsigned)rowL) * (unsigned)S_ + cbase;
    unsigned word = 0;
    for (int k = 0; k < h; k += 4) {
        const int c0 = (k     < myCount) ? Un[myStart + k]     : 0;
        const int c1 = (k + 1 < myCount) ? Un[myStart + k + 1] : 0;
        const int c2 = (k + 2 < myCount) ? Un[myStart + k + 2] : 0;
        const int c3 = (k + 3 < myCount) ? Un[myStart + k + 3] : 0;
        const unsigned bb0 = (unsigned)keep_bit(base + (unsigned)c0);
        const unsigned bb1 = (unsigned)keep_bit(base + (unsigned)c1);
        const unsigned bb2 = (unsigned)keep_bit(base + (unsigned)c2);
        const unsigned bb3 = (unsigned)keep_bit(base + (unsigned)c3);
        unsigned nib = bb0 | (bb1 << 1) | (bb2 << 2) | (bb3 << 3);
        const int rem = myCount - k;
        if (rem < 4) nib &= (rem <= 0) ? 0u : ((1u << rem) - 1u);
        word |= nib << k;
    }
    const unsigned other = __shfl_xor_sync(0xffffffffu, word, 16);
    const unsigned long long comb =
        (unsigned long long)word | ((unsigned long long)other << h);
    const unsigned w0 = (unsigned)comb;
    const unsigned w1 = (unsigned)(comb >> 32);
    a0  = __shfl_sync(0xffffffffu, w0, grp);
    a1  = __shfl_sync(0xffffffffu, w1, grp);
    b0w = __shfl_sync(0xffffffffu, w0, grp + 8);
    b1w = __shfl_sync(0xffffffffu, w1, grp + 8);
}

// ---------------------------------------------------------------------------
// Merged projection GEMM, double-buffered (tf32 mma).
// Grid 1536: rsel = bx>>9 picks {Q,K,V}; g = bx&511 picks the 128x64 tile.
// Dynamic smem: X buffers 2x(128x36), W buffers 2x(64x36) = 55296 B.
// ---------------------------------------------------------------------------
static constexpr int PROJ_XBUF = 128 * 36;
static constexpr int PROJ_WBUF = 64 * 36;
static constexpr int PROJ_SMEM_BYTES = 2 * (PROJ_XBUF + PROJ_WBUF) * 4;

__global__ void __launch_bounds__(256, 2) proj3_kernel(
    const float* __restrict__ Xq, const float* __restrict__ Xk, const float* __restrict__ Xv,
    const float* __restrict__ Wq, const float* __restrict__ Wk, const float* __restrict__ Wv,
    const float* __restrict__ bq, const float* __restrict__ bk, const float* __restrict__ bv) {
    extern __shared__ float psm[];
    float* Xb0 = psm;
    float* Xb1 = psm + PROJ_XBUF;
    float* Wb0 = psm + 2 * PROJ_XBUF;
    float* Wb1 = psm + 2 * PROJ_XBUF + PROJ_WBUF;

    const int bx = blockIdx.x;
    const int rsel = bx >> 9;
    const int g = bx & 511;
    const float* X    = (rsel == 0) ? Xq : (rsel == 1) ? Xk : Xv;
    const float* W    = (rsel == 0) ? Wq : (rsel == 1) ? Wk : Wv;
    const float* bias = (rsel == 0) ? bq : (rsel == 1) ? bk : bv;
    float*       Y    = (rsel == 0) ? g_q : (rsel == 1) ? g_k : g_v;

    const int m0 = (g & 31) << 7;
    const int n0 = (g >> 5) << 6;
    const int t  = threadIdx.x;
    const int lane = t & 31, w = t >> 5;
    const int grp = lane >> 2, qd = lane & 3;
    const int wm = w >> 1, wn = w & 1;
    const int frow = t >> 3;          // 0..31
    const int fc4  = (t & 7) << 2;    // 0..28

    const int xoff0 = (wm * 32 + grp) * 36 + qd;
    const int xoff1 = (wm * 32 + 16 + grp) * 36 + qd;
    const int woff  = (wn * 32 + grp) * 36 + qd;

    float acc[2][4][4];
    #pragma unroll
    for (int mt = 0; mt < 2; mt++)
        #pragma unroll
        for (int nt = 0; nt < 4; nt++)
            #pragma unroll
            for (int r = 0; r < 4; r++) acc[mt][nt][r] = 0.0f;

    // ---- prologue: chunk 0 G2R -> R2S(buf0) -> sync ----
    float4 xr[4], wr[2];
    #pragma unroll
    for (int l = 0; l < 4; l++)
        xr[l] = *reinterpret_cast<const float4*>(&X[(size_t)(m0 + frow + (l << 5)) * D_ + fc4]);
    #pragma unroll
    for (int l = 0; l < 2; l++)
        wr[l] = *reinterpret_cast<const float4*>(&W[(size_t)(n0 + frow + (l << 5)) * D_ + fc4]);
    #pragma unroll
    for (int l = 0; l < 4; l++) {
        float* d = &Xb0[(frow + (l << 5)) * 36 + fc4];
        d[0] = f2tf32f(xr[l].x); d[1] = f2tf32f(xr[l].y);
        d[2] = f2tf32f(xr[l].z); d[3] = f2tf32f(xr[l].w);
    }
    #pragma unroll
    for (int l = 0; l < 2; l++) {
        float* d = &Wb0[(frow + (l << 5)) * 36 + fc4];
        d[0] = f2tf32f(wr[l].x); d[1] = f2tf32f(wr[l].y);
        d[2] = f2tf32f(wr[l].z); d[3] = f2tf32f(wr[l].w);
    }
    __syncthreads();

    for (int kc = 0; kc < 32; kc++) {
        // ---- prefetch next chunk (G2R) ----
        if (kc + 1 < 32) {
            const int k0 = (kc + 1) << 5;
            #pragma unroll
            for (int l = 0; l < 4; l++)
                xr[l] = *reinterpret_cast<const float4*>(
                    &X[(size_t)(m0 + frow + (l << 5)) * D_ + k0 + fc4]);
            #pragma unroll
            for (int l = 0; l < 2; l++)
                wr[l] = *reinterpret_cast<const float4*>(
                    &W[(size_t)(n0 + frow + (l << 5)) * D_ + k0 + fc4]);
        }

        // ---- mma on current buffer ----
        const float* Xc = (kc & 1) ? Xb1 : Xb0;
        const float* Wc = (kc & 1) ? Wb1 : Wb0;
        #pragma unroll
        for (int k8 = 0; k8 < 4; k8++) {
            const int kk = k8 << 3;
            uint32_t a[2][4];
            a[0][0] = __float_as_uint(Xc[xoff0 + kk]);
            a[0][1] = __float_as_uint(Xc[xoff0 + 8 * 36 + kk]);
            a[0][2] = __float_as_uint(Xc[xoff0 + kk + 4]);
            a[0][3] = __float_as_uint(Xc[xoff0 + 8 * 36 + kk + 4]);
            a[1][0] = __float_as_uint(Xc[xoff1 + kk]);
            a[1][1] = __float_as_uint(Xc[xoff1 + 8 * 36 + kk]);
            a[1][2] = __float_as_uint(Xc[xoff1 + kk + 4]);
            a[1][3] = __float_as_uint(Xc[xoff1 + 8 * 36 + kk + 4]);
            #pragma unroll
            for (int nt = 0; nt < 4; nt++) {
                uint32_t b0 = __float_as_uint(Wc[woff + nt * 8 * 36 + kk]);
                uint32_t b1 = __float_as_uint(Wc[woff + nt * 8 * 36 + kk + 4]);
                mma_tf32(acc[0][nt], a[0][0], a[0][1], a[0][2], a[0][3], b0, b1);
                mma_tf32(acc[1][nt], a[1][0], a[1][1], a[1][2], a[1][3], b0, b1);
            }
        }

        // ---- store prefetched chunk to the other buffer (R2S) ----
        if (kc + 1 < 32) {
            float* Xn = (kc & 1) ? Xb0 : Xb1;
            float* Wn = (kc & 1) ? Wb0 : Wb1;
            #pragma unroll
            for (int l = 0; l < 4; l++) {
                float* d = &Xn[(frow + (l << 5)) * 36 + fc4];
                d[0] = f2tf32f(xr[l].x); d[1] = f2tf32f(xr[l].y);
                d[2] = f2tf32f(xr[l].z); d[3] = f2tf32f(xr[l].w);
            }
            #pragma unroll
            for (int l = 0; l < 2; l++) {
                float* d = &Wn[(frow + (l << 5)) * 36 + fc4];
                d[0] = f2tf32f(wr[l].x); d[1] = f2tf32f(wr[l].y);
                d[2] = f2tf32f(wr[l].z); d[3] = f2tf32f(wr[l].w);
            }
        }
        __syncthreads();
    }

    #pragma unroll
    for (int mt = 0; mt < 2; mt++) {
        const int r0 = m0 + wm * 32 + mt * 16 + grp;
        #pragma unroll
        for (int nt = 0; nt < 4; nt++) {
            const int c = n0 + wn * 32 + nt * 8 + (qd << 1);
            const float b0 = bias[c], b1 = bias[c + 1];
            float2 v0 = make_float2(acc[mt][nt][0] + b0, acc[mt][nt][1] + b1);
            float2 v1 = make_float2(acc[mt][nt][2] + b0, acc[mt][nt][3] + b1);
            *reinterpret_cast<float2*>(&Y[(size_t)r0 * D_ + c]) = v0;
            *reinterpret_cast<float2*>(&Y[(size_t)(r0 + 8) * D_ + c]) = v1;
        }
    }
}

// ---------------------------------------------------------------------------
// Flash attention (tf32 mma) + compacted in-loop dropout generation.
// grid (S/128, B*H), 256 thr (8 warps), 2 blocks/SM.  (identical to R12)
// ---------------------------------------------------------------------------
static constexpr int ATTN_SMEM_FLOATS = 128 * 72 + 64 * 72 + 64 * 72 + 128 * 72 + 8 + 64;
static constexpr int ATTN_SMEM_BYTES  = ATTN_SMEM_FLOATS * 4;

__global__ void __launch_bounds__(256, 2) attn_mma_kernel(const int* __restrict__ mask,
                                                          const float* __restrict__ inv_scale_p,
                                                          float* __restrict__ out) {
    extern __shared__ float sm[];
    float*    Qs = sm;
    float*    Ks = Qs + 128 * 72;
    float*    Vs = Ks + 64 * 72;
    float*    Ps = Vs + 64 * 72;
    unsigned* Binf = (unsigned*)(Ps + 128 * 72);
    int*      Un   = (int*)(Binf + 8);

    const int q0 = blockIdx.x << 7;
    const int bh = blockIdx.y;
    const int b  = bh >> 4;
    const int hcol = (bh & 15) << 6;
    const int t = threadIdx.x;
    const int lane = t & 31, w = t >> 5;
    const int grp = lane >> 2, qd = lane & 3;
    const int R0 = (w << 4) + grp;
    const int sw0 = R0 & 15, sw1 = (R0 + 8) & 15;
    const float scale = 1.0f / inv_scale_p[0];

    float* Q0 = &Qs[R0 * 72];
    float* Q1 = &Qs[(R0 + 8) * 72];
    float* P0 = &Ps[R0 * 72];
    float* P1 = &Ps[(R0 + 8) * 72];

    const unsigned wrow0 = (unsigned)bh * (unsigned)S_ + (unsigned)(q0 + (w << 4));

    {
        const int cq = t & 15;
        #pragma unroll
        for (int l = 0; l < 8; l++) {
            const int row = (t >> 4) + (l << 4);
            float4 v = *reinterpret_cast<const float4*>(
                &g_q[(size_t)(b * S_ + q0 + row) * D_ + hcol + (cq << 2)]);
            float* d = &Qs[row * 72 + ((cq ^ (row & 15)) << 2)];
            d[0] = f2tf32f(v.x); d[1] = f2tf32f(v.y); d[2] = f2tf32f(v.z); d[3] = f2tf32f(v.w);
        }
    }

    if (w == 0) {
        const int v0 = mask[b * S_ + lane];
        const int v1 = mask[b * S_ + 32 + lane];
        const unsigned bl0 = __ballot_sync(0xffffffffu, v0 != 0);
        const unsigned bl1 = __ballot_sync(0xffffffffu, v1 != 0);
        const int c0 = __popc(bl0);
        const int r0 = __popc(bl0 & ((1u << lane) - 1u));
        const int r1 = c0 + __popc(bl1 & ((1u << lane) - 1u));
        if (v0) Un[r0] = lane;
        if (v1) Un[r1] = 32 + lane;
        if (lane == 0) {
            Binf[0] = bl0; Binf[1] = bl1;
            Binf[2] = (unsigned)(c0 + __popc(bl1));
        }
    }
    __syncthreads();

    unsigned ra0, ra1, rb0w, rb1w;
    gen_words((int)Binf[2], Un, wrow0, 0u, lane, grp, ra0, ra1, rb0w, rb1w);

    float oacc[8][4];
    #pragma unroll
    for (int nt = 0; nt < 8; nt++)
        #pragma unroll
        for (int r = 0; r < 4; r++) oacc[nt][r] = 0.0f;
    float mrow0 = -INFINITY, mrow1 = -INFINITY;
    float lrow0 = 0.0f, lrow1 = 0.0f;

    for (int kt = 0; kt < S_ / 64; kt++) {
        const int kbase = kt << 6;
        __syncthreads();
        {
            const int cq = t & 15;
            #pragma unroll
            for (int l = 0; l < 4; l++) {
                const int row = (t >> 4) + (l << 4);
                const size_t gof = (size_t)(b * S_ + kbase + row) * D_ + hcol + (cq << 2);
                float4 kv = *reinterpret_cast<const float4*>(&g_k[gof]);
                float* dk = &Ks[row * 72 + ((cq ^ (row & 15)) << 2)];
                dk[0] = f2tf32f(kv.x); dk[1] = f2tf32f(kv.y);
                dk[2] = f2tf32f(kv.z); dk[3] = f2tf32f(kv.w);
                float4 vv = *reinterpret_cast<const float4*>(&g_v[gof]);
                float* dv = &Vs[row * 72 + (cq << 2)];
                dv[0] = f2tf32f(vv.x); dv[1] = f2tf32f(vv.y);
                dv[2] = f2tf32f(vv.z); dv[3] = f2tf32f(vv.w);
            }
            if (w == 0 && kt + 1 < S_ / 64) {
                const int mb = b * S_ + ((kt + 1) << 6);
                const int v0 = mask[mb + lane];
                const int v1 = mask[mb + 32 + lane];
                const unsigned bl0 = __ballot_sync(0xffffffffu, v0 != 0);
                const unsigned bl1 = __ballot_sync(0xffffffffu, v1 != 0);
                const int c0 = __popc(bl0);
                const int r0 = __popc(bl0 & ((1u << lane) - 1u));
                const int r1 = c0 + __popc(bl1 & ((1u << lane) - 1u));
                if (v0) Un[r0] = lane;
                if (v1) Un[r1] = 32 + lane;
                if (lane == 0) {
                    const int bi = ((kt + 1) & 1) << 2;
                    Binf[bi + 0] = bl0; Binf[bi + 1] = bl1;
                    Binf[bi + 2] = (unsigned)(c0 + __popc(bl1));
                }
            }
        }
        __syncthreads();

        const int cbi = (kt & 1) << 2;
        const unsigned cbl0 = Binf[cbi + 0];
        const unsigned cbl1 = Binf[cbi + 1];
        const int cu0 = __popc(cbl0);

        float sacc[8][4];
        #pragma unroll
        for (int nt = 0; nt < 8; nt++)
            #pragma unroll
            for (int r = 0; r < 4; r++) sacc[nt][r] = 0.0f;

        #pragma unroll
        for (int k8 = 0; k8 < 8; k8++) {
            const int cqa = 2 * k8;
            uint32_t a0 = __float_as_uint(Q0[((cqa ^ sw0) << 2) + qd]);
            uint32_t a1 = __float_as_uint(Q1[((cqa ^ sw1) << 2) + qd]);
            uint32_t a2 = __float_as_uint(Q0[(((cqa + 1) ^ sw0) << 2) + qd]);
            uint32_t a3 = __float_as_uint(Q1[(((cqa + 1) ^ sw1) << 2) + qd]);
            #pragma unroll
            for (int nt = 0; nt < 8; nt++) {
                const int key = (nt << 3) + grp;
                const int ksw = key & 15;
                const float* kr = &Ks[key * 72];
                uint32_t b0 = __float_as_uint(kr[((cqa ^ ksw) << 2) + qd]);
                uint32_t b1 = __float_as_uint(kr[(((cqa + 1) ^ ksw) << 2) + qd]);
                mma_tf32(sacc[nt], a0, a1, a2, a3, b0, b1);
            }
        }

        unsigned na0 = 0, na1 = 0, nb0w = 0, nb1w = 0;
        if (kt + 1 < S_ / 64) {
            const int nbi = ((kt + 1) & 1) << 2;
            gen_words((int)Binf[nbi + 2], Un, wrow0,
                      (unsigned)((kt + 1) << 6), lane, grp, na0, na1, nb0w, nb1w);
        }

        int mus0[8];
        #pragma unroll
        for (int nt = 0; nt < 8; nt++) {
            const int col = (nt << 3) + (qd << 1);
            const unsigned selw = (col < 32) ? cbl0 : cbl1;
            const int cl = col & 31;
            const int mu0 = (int)((selw >> cl) & 1u);
            const int mu1 = (int)((selw >> (cl + 1)) & 1u);
            mus0[nt] = mu0;
            sacc[nt][0] = mu0 ? sacc[nt][0] * scale : -INFINITY;
            sacc[nt][1] = mu1 ? sacc[nt][1] * scale : -INFINITY;
            sacc[nt][2] = mu0 ? sacc[nt][2] * scale : -INFINITY;
            sacc[nt][3] = mu1 ? sacc[nt][3] * scale : -INFINITY;
        }

        float mx0 = -INFINITY, mx1 = -INFINITY;
        #pragma unroll
        for (int nt = 0; nt < 8; nt++) {
            mx0 = fmaxf(mx0, fmaxf(sacc[nt][0], sacc[nt][1]));
            mx1 = fmaxf(mx1, fmaxf(sacc[nt][2], sacc[nt][3]));
        }
        #pragma unroll
        for (int o = 1; o < 4; o <<= 1) {
            mx0 = fmaxf(mx0, __shfl_xor_sync(0xffffffffu, mx0, o));
            mx1 = fmaxf(mx1, __shfl_xor_sync(0xffffffffu, mx1, o));
        }
        const float mn0 = fmaxf(mrow0, mx0);
        const float mn1 = fmaxf(mrow1, mx1);
        const float me0 = (mn0 == -INFINITY) ? 0.0f : mn0;
        const float me1 = (mn1 == -INFINITY) ? 0.0f : mn1;
        const float cf0 = (mrow0 == -INFINITY) ? ((mn0 == -INFINITY) ? 1.0f : 0.0f)
                                               : __expf(mrow0 - me0);
        const float cf1 = (mrow1 == -INFINITY) ? ((mn1 == -INFINITY) ? 1.0f : 0.0f)
                                               : __expf(mrow1 - me1);

        float rs0 = 0.0f, rs1 = 0.0f;
        #pragma unroll
        for (int nt = 0; nt < 8; nt++) {
            const int col = (nt << 3) + (qd << 1);
            const int cl = col & 31;
            const unsigned pmsk = (1u << cl) - 1u;
            const int rank0 = (col < 32) ? __popc(cbl0 & pmsk)
                                         : (cu0 + __popc(cbl1 & pmsk));
            const int rank1 = rank0 + mus0[nt];
            const unsigned wA0 = (rank0 < 32) ? ra0 : ra1;
            const unsigned wA1 = (rank1 < 32) ? ra0 : ra1;
            const unsigned wB0 = (rank0 < 32) ? rb0w : rb1w;
            const unsigned wB1 = (rank1 < 32) ? rb0w : rb1w;
            const unsigned k00 = (wA0 >> (rank0 & 31)) & 1u;
            const unsigned k01 = (wA1 >> (rank1 & 31)) & 1u;
            const unsigned k10 = (wB0 >> (rank0 & 31)) & 1u;
            const unsigned k11 = (wB1 >> (rank1 & 31)) & 1u;
            const float p00 = __expf(sacc[nt][0] - me0);
            const float p01 = __expf(sacc[nt][1] - me0);
            const float p10 = __expf(sacc[nt][2] - me1);
            const float p11 = __expf(sacc[nt][3] - me1);
            rs0 += p00 + p01;
            rs1 += p10 + p11;
            const float d00 = k00 ? p00 * (1.0f / 0.9f) : 0.0f;
            const float d01 = k01 ? p01 * (1.0f / 0.9f) : 0.0f;
            const float d10 = k10 ? p10 * (1.0f / 0.9f) : 0.0f;
            const float d11 = k11 ? p11 * (1.0f / 0.9f) : 0.0f;
            const int pcq = (nt << 1) + (qd >> 1);
            const int lo  = (qd & 1) << 1;
            *reinterpret_cast<float2*>(&P0[((pcq ^ sw0) << 2) + lo]) =
                make_float2(f2tf32f(d00), f2tf32f(d01));
            *reinterpret_cast<float2*>(&P1[((pcq ^ sw1) << 2) + lo]) =
                make_float2(f2tf32f(d10), f2tf32f(d11));
        }
        #pragma unroll
        for (int o = 1; o < 4; o <<= 1) {
            rs0 += __shfl_xor_sync(0xffffffffu, rs0, o);
            rs1 += __shfl_xor_sync(0xffffffffu, rs1, o);
        }
        lrow0 = lrow0 * cf0 + rs0;
        lrow1 = lrow1 * cf1 + rs1;
        mrow0 = mn0;
        mrow1 = mn1;
        #pragma unroll
        for (int nt = 0; nt < 8; nt++) {
            oacc[nt][0] *= cf0; oacc[nt][1] *= cf0;
            oacc[nt][2] *= cf1; oacc[nt][3] *= cf1;
        }
        __syncwarp();

        #pragma unroll
        for (int k8 = 0; k8 < 8; k8++) {
            const int cqa = 2 * k8;
            uint32_t a0 = __float_as_uint(P0[((cqa ^ sw0) << 2) + qd]);
            uint32_t a1 = __float_as_uint(P1[((cqa ^ sw1) << 2) + qd]);
            uint32_t a2 = __float_as_uint(P0[(((cqa + 1) ^ sw0) << 2) + qd]);
            uint32_t a3 = __float_as_uint(P1[(((cqa + 1) ^ sw1) << 2) + qd]);
            const float* v0 = &Vs[((k8 << 3) + qd) * 72 + grp];
            #pragma unroll
            for (int nt = 0; nt < 8; nt++) {
                uint32_t b0 = __float_as_uint(v0[nt << 3]);
                uint32_t b1 = __float_as_uint(v0[4 * 72 + (nt << 3)]);
                mma_tf32(oacc[nt], a0, a1, a2, a3, b0, b1);
            }
        }

        ra0 = na0; ra1 = na1; rb0w = nb0w; rb1w = nb1w;
    }

    const float il0 = 1.0f / lrow0;
    const float il1 = 1.0f / lrow1;
    const size_t g0 = ((size_t)bh * S_ + q0 + R0) * HD_;
    const size_t g1 = ((size_t)bh * S_ + q0 + R0 + 8) * HD_;
    #pragma unroll
    for (int nt = 0; nt < 8; nt++) {
        const int col = (nt << 3) + (qd << 1);
        *reinterpret_cast<float2*>(&out[g0 + col]) =
            make_float2(oacc[nt][0] * il0, oacc[nt][1] * il0);
        *reinterpret_cast<float2*>(&out[g1 + col]) =
            make_float2(oacc[nt][2] * il1, oacc[nt][3] * il1);
    }
}

// ---------------------------------------------------------------------------
extern "C" void kernel_launch(void* const* d_in, const int* in_sizes, int n_in,
                              void* d_out, int out_size) {
    (void)in_sizes; (void)n_in; (void)out_size;
    const float* query = (const float*)d_in[0];
    const float* key   = (const float*)d_in[1];
    const float* value = (const float*)d_in[2];
    const int*   mask  = (const int*)d_in[3];
    const float* invsc = (const float*)d_in[4];
    const float* Wq    = (const float*)d_in[5];
    const float* bq    = (const float*)d_in[6];
    const float* Wk    = (const float*)d_in[7];
    const float* bk    = (const float*)d_in[8];
    const float* Wv    = (const float*)d_in[9];
    const float* bv    = (const float*)d_in[10];
    float*       out   = (float*)d_out;

    cudaFuncSetAttribute(proj3_kernel, cudaFuncAttributeMaxDynamicSharedMemorySize,
                         PROJ_SMEM_BYTES);
    proj3_kernel<<<1536, 256, PROJ_SMEM_BYTES>>>(query, key, value,
                                                 Wq, Wk, Wv, bq, bk, bv);

    cudaFuncSetAttribute(attn_mma_kernel, cudaFuncAttributeMaxDynamicSharedMemorySize,
                         ATTN_SMEM_BYTES);
    dim3 ag(S_ / 128, B_ * H_);
    attn_mma_kernel<<<ag, 256, ATTN_SMEM_BYTES>>>(mask, invsc, out);
}

// round 14
// speedup vs baseline: 1.8278x; 1.0453x over previous
#include <cuda_runtime.h>
#include <cstdint>
#include <math.h>

// ============================================================================
// AttentionModel: QKV projection + MHA + jax-threefry dropout.
//   B=2, S=2048, D=1024, H=16, HD=64
// Round 14: P smem roundtrip eliminated — S-accumulator fragments are
// permuted into PV A-fragments with warp shuffles (8 shfl + 4 selects per
// k-group), dropout+PV loops fused, Ps removed from smem (110.8->73.8 KB).
// Projection: R13 double-buffered tf32 GEMM (unchanged).
// ============================================================================

static constexpr int B_ = 2, H_ = 16, S_ = 2048, D_ = 1024, HD_ = 64;

__device__ float g_q[B_ * S_ * D_];
__device__ float g_k[B_ * S_ * D_];
__device__ float g_v[B_ * S_ * D_];

// ---------------------------------------------------------------------------
// tf32 helpers
// ---------------------------------------------------------------------------
__device__ __forceinline__ float f2tf32f(float x) {
    uint32_t r;
    asm("cvt.rna.tf32.f32 %0, %1;" : "=r"(r) : "f"(x));
    return __uint_as_float(r);
}

__device__ __forceinline__ void mma_tf32(float c[4],
                                         uint32_t a0, uint32_t a1, uint32_t a2, uint32_t a3,
                                         uint32_t b0, uint32_t b1) {
    asm volatile(
        "mma.sync.aligned.m16n8k8.row.col.f32.tf32.tf32.f32 "
        "{%0,%1,%2,%3}, {%4,%5,%6,%7}, {%8,%9}, {%0,%1,%2,%3};"
        : "+f"(c[0]), "+f"(c[1]), "+f"(c[2]), "+f"(c[3])
        : "r"(a0), "r"(a1), "r"(a2), "r"(a3), "r"(b0), "r"(b1));
}

// ---------------------------------------------------------------------------
// Threefry-2x32 (JAX partitionable) — verified exact in Round 2.
// keep(idx) <=> bits < 3865470464u (exact integer form of u < 0.9f).
// ---------------------------------------------------------------------------
struct KeyPair { unsigned a, b; };

__host__ __device__ constexpr unsigned rotlc(unsigned x, int r) {
    return (x << r) | (x >> (32 - r));
}

__host__ __device__ constexpr KeyPair threefry_block(unsigned k0, unsigned k1,
                                                     unsigned x0, unsigned x1) {
    unsigned k2 = k0 ^ k1 ^ 0x1BD11BDAu;
    x0 += k0; x1 += k1;
    const int RA[4] = {13, 15, 26, 6};
    const int RB[4] = {17, 29, 16, 24};
    for (int i = 0; i < 4; i++) { x0 += x1; x1 = rotlc(x1, RA[i]); x1 ^= x0; }
    x0 += k1; x1 += k2 + 1u;
    for (int i = 0; i < 4; i++) { x0 += x1; x1 = rotlc(x1, RB[i]); x1 ^= x0; }
    x0 += k2; x1 += k0 + 2u;
    for (int i = 0; i < 4; i++) { x0 += x1; x1 = rotlc(x1, RA[i]); x1 ^= x0; }
    x0 += k0; x1 += k1 + 3u;
    for (int i = 0; i < 4; i++) { x0 += x1; x1 = rotlc(x1, RB[i]); x1 ^= x0; }
    x0 += k1; x1 += k2 + 4u;
    for (int i = 0; i < 4; i++) { x0 += x1; x1 = rotlc(x1, RA[i]); x1 ^= x0; }
    x0 += k2; x1 += k0 + 5u;
    return {x0, x1};
}

__device__ __forceinline__ bool keep_bit(unsigned idx) {
    constexpr KeyPair FK = threefry_block(0u, 0u, 0u, 12345u);
    KeyPair r = threefry_block(FK.a, FK.b, 0u, idx);
    return (r.a ^ r.b) < 3865470464u;
}

// ---------------------------------------------------------------------------
// Rank-compacted dropout-word generation, 4 hash chains per iteration.
// ---------------------------------------------------------------------------
__device__ __forceinline__ void gen_words(int u, const int* __restrict__ Un,
                                          unsigned wrow0, unsigned cbase,
                                          int lane, int grp,
                                          unsigned& a0, unsigned& a1,
                                          unsigned& b0w, unsigned& b1w) {
    const int h = (u + 1) >> 1;
    const int rowL = lane & 15;
    const int halfS = lane >> 4;
    const int myStart = halfS ? h : 0;
    const int myCount = halfS ? (u - h) : h;
    const unsigned base = (wrow0 + (unsigned)rowL) * (unsigned)S_ + cbase;
    unsigned word = 0;
    for (int k = 0; k < h; k += 4) {
        const int c0 = (k     < myCount) ? Un[myStart + k]     : 0;
        const int c1 = (k + 1 < myCount) ? Un[myStart + k + 1] : 0;
        const int c2 = (k + 2 < myCount) ? Un[myStart + k + 2] : 0;
        const int c3 = (k + 3 < myCount) ? Un[myStart + k + 3] : 0;
        const unsigned bb0 = (unsigned)keep_bit(base + (unsigned)c0);
        const unsigned bb1 = (unsigned)keep_bit(base + (unsigned)c1);
        const unsigned bb2 = (unsigned)keep_bit(base + (unsigned)c2);
        const unsigned bb3 = (unsigned)keep_bit(base + (unsigned)c3);
        unsigned nib = bb0 | (bb1 << 1) | (bb2 << 2) | (bb3 << 3);
        const int rem = myCount - k;
        if (rem < 4) nib &= (rem <= 0) ? 0u : ((1u << rem) - 1u);
        word |= nib << k;
    }
    const unsigned other = __shfl_xor_sync(0xffffffffu, word, 16);
    const unsigned long long comb =
        (unsigned long long)word | ((unsigned long long)other << h);
    const unsigned w0 = (unsigned)comb;
    const unsigned w1 = (unsigned)(comb >> 32);
    a0  = __shfl_sync(0xffffffffu, w0, grp);
    a1  = __shfl_sync(0xffffffffu, w1, grp);
    b0w = __shfl_sync(0xffffffffu, w0, grp + 8);
    b1w = __shfl_sync(0xffffffffu, w1, grp + 8);
}

// ---------------------------------------------------------------------------
// Merged projection GEMM, double-buffered (tf32 mma).  (R13, unchanged)
// ---------------------------------------------------------------------------
static constexpr int PROJ_XBUF = 128 * 36;
static constexpr int PROJ_WBUF = 64 * 36;
static constexpr int PROJ_SMEM_BYTES = 2 * (PROJ_XBUF + PROJ_WBUF) * 4;

__global__ void __launch_bounds__(256, 2) proj3_kernel(
    const float* __restrict__ Xq, const float* __restrict__ Xk, const float* __restrict__ Xv,
    const float* __restrict__ Wq, const float* __restrict__ Wk, const float* __restrict__ Wv,
    const float* __restrict__ bq, const float* __restrict__ bk, const float* __restrict__ bv) {
    extern __shared__ float psm[];
    float* Xb0 = psm;
    float* Xb1 = psm + PROJ_XBUF;
    float* Wb0 = psm + 2 * PROJ_XBUF;
    float* Wb1 = psm + 2 * PROJ_XBUF + PROJ_WBUF;

    const int bx = blockIdx.x;
    const int rsel = bx >> 9;
    const int g = bx & 511;
    const float* X    = (rsel == 0) ? Xq : (rsel == 1) ? Xk : Xv;
    const float* W    = (rsel == 0) ? Wq : (rsel == 1) ? Wk : Wv;
    const float* bias = (rsel == 0) ? bq : (rsel == 1) ? bk : bv;
    float*       Y    = (rsel == 0) ? g_q : (rsel == 1) ? g_k : g_v;

    const int m0 = (g & 31) << 7;
    const int n0 = (g >> 5) << 6;
    const int t  = threadIdx.x;
    const int lane = t & 31, w = t >> 5;
    const int grp = lane >> 2, qd = lane & 3;
    const int wm = w >> 1, wn = w & 1;
    const int frow = t >> 3;
    const int fc4  = (t & 7) << 2;

    const int xoff0 = (wm * 32 + grp) * 36 + qd;
    const int xoff1 = (wm * 32 + 16 + grp) * 36 + qd;
    const int woff  = (wn * 32 + grp) * 36 + qd;

    float acc[2][4][4];
    #pragma unroll
    for (int mt = 0; mt < 2; mt++)
        #pragma unroll
        for (int nt = 0; nt < 4; nt++)
            #pragma unroll
            for (int r = 0; r < 4; r++) acc[mt][nt][r] = 0.0f;

    float4 xr[4], wr[2];
    #pragma unroll
    for (int l = 0; l < 4; l++)
        xr[l] = *reinterpret_cast<const float4*>(&X[(size_t)(m0 + frow + (l << 5)) * D_ + fc4]);
    #pragma unroll
    for (int l = 0; l < 2; l++)
        wr[l] = *reinterpret_cast<const float4*>(&W[(size_t)(n0 + frow + (l << 5)) * D_ + fc4]);
    #pragma unroll
    for (int l = 0; l < 4; l++) {
        float* d = &Xb0[(frow + (l << 5)) * 36 + fc4];
        d[0] = f2tf32f(xr[l].x); d[1] = f2tf32f(xr[l].y);
        d[2] = f2tf32f(xr[l].z); d[3] = f2tf32f(xr[l].w);
    }
    #pragma unroll
    for (int l = 0; l < 2; l++) {
        float* d = &Wb0[(frow + (l << 5)) * 36 + fc4];
        d[0] = f2tf32f(wr[l].x); d[1] = f2tf32f(wr[l].y);
        d[2] = f2tf32f(wr[l].z); d[3] = f2tf32f(wr[l].w);
    }
    __syncthreads();

    for (int kc = 0; kc < 32; kc++) {
        if (kc + 1 < 32) {
            const int k0 = (kc + 1) << 5;
            #pragma unroll
            for (int l = 0; l < 4; l++)
                xr[l] = *reinterpret_cast<const float4*>(
                    &X[(size_t)(m0 + frow + (l << 5)) * D_ + k0 + fc4]);
            #pragma unroll
            for (int l = 0; l < 2; l++)
                wr[l] = *reinterpret_cast<const float4*>(
                    &W[(size_t)(n0 + frow + (l << 5)) * D_ + k0 + fc4]);
        }

        const float* Xc = (kc & 1) ? Xb1 : Xb0;
        const float* Wc = (kc & 1) ? Wb1 : Wb0;
        #pragma unroll
        for (int k8 = 0; k8 < 4; k8++) {
            const int kk = k8 << 3;
            uint32_t a[2][4];
            a[0][0] = __float_as_uint(Xc[xoff0 + kk]);
            a[0][1] = __float_as_uint(Xc[xoff0 + 8 * 36 + kk]);
            a[0][2] = __float_as_uint(Xc[xoff0 + kk + 4]);
            a[0][3] = __float_as_uint(Xc[xoff0 + 8 * 36 + kk + 4]);
            a[1][0] = __float_as_uint(Xc[xoff1 + kk]);
            a[1][1] = __float_as_uint(Xc[xoff1 + 8 * 36 + kk]);
            a[1][2] = __float_as_uint(Xc[xoff1 + kk + 4]);
            a[1][3] = __float_as_uint(Xc[xoff1 + 8 * 36 + kk + 4]);
            #pragma unroll
            for (int nt = 0; nt < 4; nt++) {
                uint32_t b0 = __float_as_uint(Wc[woff + nt * 8 * 36 + kk]);
                uint32_t b1 = __float_as_uint(Wc[woff + nt * 8 * 36 + kk + 4]);
                mma_tf32(acc[0][nt], a[0][0], a[0][1], a[0][2], a[0][3], b0, b1);
                mma_tf32(acc[1][nt], a[1][0], a[1][1], a[1][2], a[1][3], b0, b1);
            }
        }

        if (kc + 1 < 32) {
            float* Xn = (kc & 1) ? Xb0 : Xb1;
            float* Wn = (kc & 1) ? Wb0 : Wb1;
            #pragma unroll
            for (int l = 0; l < 4; l++) {
                float* d = &Xn[(frow + (l << 5)) * 36 + fc4];
                d[0] = f2tf32f(xr[l].x); d[1] = f2tf32f(xr[l].y);
                d[2] = f2tf32f(xr[l].z); d[3] = f2tf32f(xr[l].w);
            }
            #pragma unroll
            for (int l = 0; l < 2; l++) {
                float* d = &Wn[(frow + (l << 5)) * 36 + fc4];
                d[0] = f2tf32f(wr[l].x); d[1] = f2tf32f(wr[l].y);
                d[2] = f2tf32f(wr[l].z); d[3] = f2tf32f(wr[l].w);
            }
        }
        __syncthreads();
    }

    #pragma unroll
    for (int mt = 0; mt < 2; mt++) {
        const int r0 = m0 + wm * 32 + mt * 16 + grp;
        #pragma unroll
        for (int nt = 0; nt < 4; nt++) {
            const int c = n0 + wn * 32 + nt * 8 + (qd << 1);
            const float b0 = bias[c], b1 = bias[c + 1];
            float2 v0 = make_float2(acc[mt][nt][0] + b0, acc[mt][nt][1] + b1);
            float2 v1 = make_float2(acc[mt][nt][2] + b0, acc[mt][nt][3] + b1);
            *reinterpret_cast<float2*>(&Y[(size_t)r0 * D_ + c]) = v0;
            *reinterpret_cast<float2*>(&Y[(size_t)(r0 + 8) * D_ + c]) = v1;
        }
    }
}

// ---------------------------------------------------------------------------
// Flash attention (tf32 mma), shuffle-based PV A-fragments (no P smem).
// grid (S/128, B*H), 256 thr (8 warps), 2 blocks/SM.
// smem: Qs[128][72] | Ks[64][72] | Vs[64][72] | Binf[2][4] | Un[64] = 73.9 KB
// ---------------------------------------------------------------------------
static constexpr int ATTN_SMEM_FLOATS = 128 * 72 + 64 * 72 + 64 * 72 + 8 + 64;
static constexpr int ATTN_SMEM_BYTES  = ATTN_SMEM_FLOATS * 4;

__global__ void __launch_bounds__(256, 2) attn_mma_kernel(const int* __restrict__ mask,
                                                          const float* __restrict__ inv_scale_p,
                                                          float* __restrict__ out) {
    extern __shared__ float sm[];
    float*    Qs = sm;
    float*    Ks = Qs + 128 * 72;
    float*    Vs = Ks + 64 * 72;
    unsigned* Binf = (unsigned*)(Vs + 64 * 72);
    int*      Un   = (int*)(Binf + 8);

    const int q0 = blockIdx.x << 7;
    const int bh = blockIdx.y;
    const int b  = bh >> 4;
    const int hcol = (bh & 15) << 6;
    const int t = threadIdx.x;
    const int lane = t & 31, w = t >> 5;
    const int grp = lane >> 2, qd = lane & 3;
    const int R0 = (w << 4) + grp;
    const int sw0 = R0 & 15, sw1 = (R0 + 8) & 15;
    const float scale = 1.0f / inv_scale_p[0];

    float* Q0 = &Qs[R0 * 72];
    float* Q1 = &Qs[(R0 + 8) * 72];

    // shuffle source lanes for C->A fragment permutation (quad-local)
    const int srcA = (lane & ~3) | (qd >> 1);
    const int srcB = srcA + 2;
    const bool oddq = (qd & 1) != 0;

    const unsigned wrow0 = (unsigned)bh * (unsigned)S_ + (unsigned)(q0 + (w << 4));

    {
        const int cq = t & 15;
        #pragma unroll
        for (int l = 0; l < 8; l++) {
            const int row = (t >> 4) + (l << 4);
            float4 v = *reinterpret_cast<const float4*>(
                &g_q[(size_t)(b * S_ + q0 + row) * D_ + hcol + (cq << 2)]);
            float* d = &Qs[row * 72 + ((cq ^ (row & 15)) << 2)];
            d[0] = f2tf32f(v.x); d[1] = f2tf32f(v.y); d[2] = f2tf32f(v.z); d[3] = f2tf32f(v.w);
        }
    }

    if (w == 0) {
        const int v0 = mask[b * S_ + lane];
        const int v1 = mask[b * S_ + 32 + lane];
        const unsigned bl0 = __ballot_sync(0xffffffffu, v0 != 0);
        const unsigned bl1 = __ballot_sync(0xffffffffu, v1 != 0);
        const int c0 = __popc(bl0);
        const int r0 = __popc(bl0 & ((1u << lane) - 1u));
        const int r1 = c0 + __popc(bl1 & ((1u << lane) - 1u));
        if (v0) Un[r0] = lane;
        if (v1) Un[r1] = 32 + lane;
        if (lane == 0) {
            Binf[0] = bl0; Binf[1] = bl1;
            Binf[2] = (unsigned)(c0 + __popc(bl1));
        }
    }
    __syncthreads();

    unsigned ra0, ra1, rb0w, rb1w;
    gen_words((int)Binf[2], Un, wrow0, 0u, lane, grp, ra0, ra1, rb0w, rb1w);

    float oacc[8][4];
    #pragma unroll
    for (int nt = 0; nt < 8; nt++)
        #pragma unroll
        for (int r = 0; r < 4; r++) oacc[nt][r] = 0.0f;
    float mrow0 = -INFINITY, mrow1 = -INFINITY;
    float lrow0 = 0.0f, lrow1 = 0.0f;

    for (int kt = 0; kt < S_ / 64; kt++) {
        const int kbase = kt << 6;
        __syncthreads();
        {
            const int cq = t & 15;
            #pragma unroll
            for (int l = 0; l < 4; l++) {
                const int row = (t >> 4) + (l << 4);
                const size_t gof = (size_t)(b * S_ + kbase + row) * D_ + hcol + (cq << 2);
                float4 kv = *reinterpret_cast<const float4*>(&g_k[gof]);
                float* dk = &Ks[row * 72 + ((cq ^ (row & 15)) << 2)];
                dk[0] = f2tf32f(kv.x); dk[1] = f2tf32f(kv.y);
                dk[2] = f2tf32f(kv.z); dk[3] = f2tf32f(kv.w);
                float4 vv = *reinterpret_cast<const float4*>(&g_v[gof]);
                float* dv = &Vs[row * 72 + (cq << 2)];
                dv[0] = f2tf32f(vv.x); dv[1] = f2tf32f(vv.y);
                dv[2] = f2tf32f(vv.z); dv[3] = f2tf32f(vv.w);
            }
            if (w == 0 && kt + 1 < S_ / 64) {
                const int mb = b * S_ + ((kt + 1) << 6);
                const int v0 = mask[mb + lane];
                const int v1 = mask[mb + 32 + lane];
                const unsigned bl0 = __ballot_sync(0xffffffffu, v0 != 0);
                const unsigned bl1 = __ballot_sync(0xffffffffu, v1 != 0);
                const int c0 = __popc(bl0);
                const int r0 = __popc(bl0 & ((1u << lane) - 1u));
                const int r1 = c0 + __popc(bl1 & ((1u << lane) - 1u));
                if (v0) Un[r0] = lane;
                if (v1) Un[r1] = 32 + lane;
                if (lane == 0) {
                    const int bi = ((kt + 1) & 1) << 2;
                    Binf[bi + 0] = bl0; Binf[bi + 1] = bl1;
                    Binf[bi + 2] = (unsigned)(c0 + __popc(bl1));
                }
            }
        }
        __syncthreads();

        const int cbi = (kt & 1) << 2;
        const unsigned cbl0 = Binf[cbi + 0];
        const unsigned cbl1 = Binf[cbi + 1];
        const int cu0 = __popc(cbl0);

        // ---- S = Q K^T ----
        float sacc[8][4];
        #pragma unroll
        for (int nt = 0; nt < 8; nt++)
            #pragma unroll
            for (int r = 0; r < 4; r++) sacc[nt][r] = 0.0f;

        #pragma unroll
        for (int k8 = 0; k8 < 8; k8++) {
            const int cqa = 2 * k8;
            uint32_t a0 = __float_as_uint(Q0[((cqa ^ sw0) << 2) + qd]);
            uint32_t a1 = __float_as_uint(Q1[((cqa ^ sw1) << 2) + qd]);
            uint32_t a2 = __float_as_uint(Q0[(((cqa + 1) ^ sw0) << 2) + qd]);
            uint32_t a3 = __float_as_uint(Q1[(((cqa + 1) ^ sw1) << 2) + qd]);
            #pragma unroll
            for (int nt = 0; nt < 8; nt++) {
                const int key = (nt << 3) + grp;
                const int ksw = key & 15;
                const float* kr = &Ks[key * 72];
                uint32_t b0 = __float_as_uint(kr[((cqa ^ ksw) << 2) + qd]);
                uint32_t b1 = __float_as_uint(kr[(((cqa + 1) ^ ksw) << 2) + qd]);
                mma_tf32(sacc[nt], a0, a1, a2, a3, b0, b1);
            }
        }

        // ---- generate NEXT tile's compacted dropout words ----
        unsigned na0 = 0, na1 = 0, nb0w = 0, nb1w = 0;
        if (kt + 1 < S_ / 64) {
            const int nbi = ((kt + 1) & 1) << 2;
            gen_words((int)Binf[nbi + 2], Un, wrow0,
                      (unsigned)((kt + 1) << 6), lane, grp, na0, na1, nb0w, nb1w);
        }

        // ---- mask + scale ----
        int mus0[8];
        #pragma unroll
        for (int nt = 0; nt < 8; nt++) {
            const int col = (nt << 3) + (qd << 1);
            const unsigned selw = (col < 32) ? cbl0 : cbl1;
            const int cl = col & 31;
            const int mu0 = (int)((selw >> cl) & 1u);
            const int mu1 = (int)((selw >> (cl + 1)) & 1u);
            mus0[nt] = mu0;
            sacc[nt][0] = mu0 ? sacc[nt][0] * scale : -INFINITY;
            sacc[nt][1] = mu1 ? sacc[nt][1] * scale : -INFINITY;
            sacc[nt][2] = mu0 ? sacc[nt][2] * scale : -INFINITY;
            sacc[nt][3] = mu1 ? sacc[nt][3] * scale : -INFINITY;
        }

        // ---- row max (quad shuffle) ----
        float mx0 = -INFINITY, mx1 = -INFINITY;
        #pragma unroll
        for (int nt = 0; nt < 8; nt++) {
            mx0 = fmaxf(mx0, fmaxf(sacc[nt][0], sacc[nt][1]));
            mx1 = fmaxf(mx1, fmaxf(sacc[nt][2], sacc[nt][3]));
        }
        #pragma unroll
        for (int o = 1; o < 4; o <<= 1) {
            mx0 = fmaxf(mx0, __shfl_xor_sync(0xffffffffu, mx0, o));
            mx1 = fmaxf(mx1, __shfl_xor_sync(0xffffffffu, mx1, o));
        }
        const float mn0 = fmaxf(mrow0, mx0);
        const float mn1 = fmaxf(mrow1, mx1);
        const float me0 = (mn0 == -INFINITY) ? 0.0f : mn0;
        const float me1 = (mn1 == -INFINITY) ? 0.0f : mn1;
        const float cf0 = (mrow0 == -INFINITY) ? ((mn0 == -INFINITY) ? 1.0f : 0.0f)
                                               : __expf(mrow0 - me0);
        const float cf1 = (mrow1 == -INFINITY) ? ((mn1 == -INFINITY) ? 1.0f : 0.0f)
                                               : __expf(mrow1 - me1);
        mrow0 = mn0;
        mrow1 = mn1;
        #pragma unroll
        for (int nt = 0; nt < 8; nt++) {
            oacc[nt][0] *= cf0; oacc[nt][1] *= cf0;
            oacc[nt][2] *= cf1; oacc[nt][3] *= cf1;
        }

        // ---- fused: exp, dropout, C->A shuffle, PV mma per k-group ----
        float rs0 = 0.0f, rs1 = 0.0f;
        #pragma unroll
        for (int nt = 0; nt < 8; nt++) {
            const int col = (nt << 3) + (qd << 1);
            const int cl = col & 31;
            const unsigned pmsk = (1u << cl) - 1u;
            const int rank0 = (col < 32) ? __popc(cbl0 & pmsk)
                                         : (cu0 + __popc(cbl1 & pmsk));
            const int rank1 = rank0 + mus0[nt];
            const unsigned wA0 = (rank0 < 32) ? ra0 : ra1;
            const unsigned wA1 = (rank1 < 32) ? ra0 : ra1;
            const unsigned wB0 = (rank0 < 32) ? rb0w : rb1w;
            const unsigned wB1 = (rank1 < 32) ? rb0w : rb1w;
            const unsigned k00 = (wA0 >> (rank0 & 31)) & 1u;
            const unsigned k01 = (wA1 >> (rank1 & 31)) & 1u;
            const unsigned k10 = (wB0 >> (rank0 & 31)) & 1u;
            const unsigned k11 = (wB1 >> (rank1 & 31)) & 1u;
            const float p00 = __expf(sacc[nt][0] - me0);
            const float p01 = __expf(sacc[nt][1] - me0);
            const float p10 = __expf(sacc[nt][2] - me1);
            const float p11 = __expf(sacc[nt][3] - me1);
            rs0 += p00 + p01;
            rs1 += p10 + p11;
            const float d00 = k00 ? p00 * (1.0f / 0.9f) : 0.0f;
            const float d01 = k01 ? p01 * (1.0f / 0.9f) : 0.0f;
            const float d10 = k10 ? p10 * (1.0f / 0.9f) : 0.0f;
            const float d11 = k11 ? p11 * (1.0f / 0.9f) : 0.0f;

            // C-fragment -> A-fragment permutation (k-group = nt)
            const float e00 = __shfl_sync(0xffffffffu, d00, srcA);
            const float e01 = __shfl_sync(0xffffffffu, d01, srcA);
            const float e02 = __shfl_sync(0xffffffffu, d00, srcB);
            const float e03 = __shfl_sync(0xffffffffu, d01, srcB);
            const float f00 = __shfl_sync(0xffffffffu, d10, srcA);
            const float f01 = __shfl_sync(0xffffffffu, d11, srcA);
            const float f02 = __shfl_sync(0xffffffffu, d10, srcB);
            const float f03 = __shfl_sync(0xffffffffu, d11, srcB);
            const uint32_t pa0 = __float_as_uint(f2tf32f(oddq ? e01 : e00));
            const uint32_t pa1 = __float_as_uint(f2tf32f(oddq ? f01 : f00));
            const uint32_t pa2 = __float_as_uint(f2tf32f(oddq ? e03 : e02));
            const uint32_t pa3 = __float_as_uint(f2tf32f(oddq ? f03 : f02));

            const float* v0 = &Vs[((nt << 3) + qd) * 72 + grp];
            #pragma unroll
            for (int dt = 0; dt < 8; dt++) {
                uint32_t b0 = __float_as_uint(v0[dt << 3]);
                uint32_t b1 = __float_as_uint(v0[4 * 72 + (dt << 3)]);
                mma_tf32(oacc[dt], pa0, pa1, pa2, pa3, b0, b1);
            }
        }
        #pragma unroll
        for (int o = 1; o < 4; o <<= 1) {
            rs0 += __shfl_xor_sync(0xffffffffu, rs0, o);
            rs1 += __shfl_xor_sync(0xffffffffu, rs1, o);
        }
        lrow0 = lrow0 * cf0 + rs0;
        lrow1 = lrow1 * cf1 + rs1;

        ra0 = na0; ra1 = na1; rb0w = nb0w; rb1w = nb1w;
    }

    const float il0 = 1.0f / lrow0;
    const float il1 = 1.0f / lrow1;
    const size_t g0 = ((size_t)bh * S_ + q0 + R0) * HD_;
    const size_t g1 = ((size_t)bh * S_ + q0 + R0 + 8) * HD_;
    #pragma unroll
    for (int nt = 0; nt < 8; nt++) {
        const int col = (nt << 3) + (qd << 1);
        *reinterpret_cast<float2*>(&out[g0 + col]) =
            make_float2(oacc[nt][0] * il0, oacc[nt][1] * il0);
        *reinterpret_cast<float2*>(&out[g1 + col]) =
            make_float2(oacc[nt][2] * il1, oacc[nt][3] * il1);
    }
}

// ---------------------------------------------------------------------------
extern "C" void kernel_launch(void* const* d_in, const int* in_sizes, int n_in,
                              void* d_out, int out_size) {
    (void)in_sizes; (void)n_in; (void)out_size;
    const float* query = (const float*)d_in[0];
    const float* key   = (const float*)d_in[1];
    const float* value = (const float*)d_in[2];
    const int*   mask  = (const int*)d_in[3];
    const float* invsc = (const float*)d_in[4];
    const float* Wq    = (const float*)d_in[5];
    const float* bq    = (const float*)d_in[6];
    const float* Wk    = (const float*)d_in[7];
    const float* bk    = (const float*)d_in[8];
    const float* Wv    = (const float*)d_in[9];
    const float* bv    = (const float*)d_in[10];
    float*       out   = (float*)d_out;

    cudaFuncSetAttribute(proj3_kernel, cudaFuncAttributeMaxDynamicSharedMemorySize,
                         PROJ_SMEM_BYTES);
    proj3_kernel<<<1536, 256, PROJ_SMEM_BYTES>>>(query, key, value,
                                                 Wq, Wk, Wv, bq, bk, bv);

    cudaFuncSetAttribute(attn_mma_kernel, cudaFuncAttributeMaxDynamicSharedMemorySize,
                         ATTN_SMEM_BYTES);
    dim3 ag(S_ / 128, B_ * H_);
    attn_mma_kernel<<<ag, 256, ATTN_SMEM_BYTES>>>(mask, invsc, out);
}